// round 3
// baseline (speedup 1.0000x reference)
#include <cuda_runtime.h>
#include <math.h>
#include <stdint.h>

#define NFFT 8192
#define LSEQ 8192
#define DM   768
#define BATCH 4
#define TFFT 512
#define SMEM_BYTES ((NFFT*2 + 2048) * (int)sizeof(float2))  // 147456

// ---------------- scratch (device globals; no runtime allocation) ----------------
__device__ __align__(16) float  g_h3[LSEQ * 64];        // 2 MB
__device__ __align__(16) float  g_k [DM * LSEQ];        // 25 MB, d-major
__device__ __align__(16) float2 g_Kf[DM * 8200];        // 50 MB, half-spectra (0..8192), stride 8200

// ---------------- complex helpers ----------------
__device__ __forceinline__ float2 cmul(float2 a, float2 b) {
    return make_float2(a.x*b.x - a.y*b.y, a.x*b.y + a.y*b.x);
}
__device__ __forceinline__ float2 cadd(float2 a, float2 b) { return make_float2(a.x+b.x, a.y+b.y); }
__device__ __forceinline__ float2 csub(float2 a, float2 b) { return make_float2(a.x-b.x, a.y-b.y); }

// ---------------- 8192-pt complex FFT, radix-4 Stockham DIF, smem ping-pong ----------
// Input in b0 (natural order), result lands in b1 (natural order).
// tw[j] = exp(-2*pi*i*j/8192), j in [0,2048)
// INV=0: forward DFT (e^{-i}); INV=1: unscaled inverse DFT (e^{+i}).
template<int INV>
__device__ __forceinline__ void fft8k(float2* b0, float2* b1, const float2* __restrict__ tw, int tid)
{
    float2* x = b0;
    float2* y = b1;
    int ls = 0;  // log2(s)
    #pragma unroll 1
    for (int stage = 0; stage < 6; stage++) {
        const int s = 1 << ls;
        #pragma unroll
        for (int idx = tid; idx < NFFT/4; idx += TFFT) {
            const int q = idx & (s - 1);
            const int p = idx >> ls;
            float2 w1 = tw[p * s];
            if (INV) w1.y = -w1.y;
            const float2 w2 = cmul(w1, w1);
            const float2 w3 = cmul(w1, w2);

            // reads: base = q + s*p == idx  (stride-1, conflict-free)
            const float2 A = x[idx];
            const float2 B = x[idx + 2048];
            const float2 C = x[idx + 4096];
            const float2 D = x[idx + 6144];

            const float2 apc = cadd(A, C);
            const float2 amc = csub(A, C);
            const float2 bpd = cadd(B, D);
            const float2 bmd = csub(B, D);
            const float2 jb  = make_float2(-bmd.y, bmd.x);  // i * bmd

            float2 t1, t3;
            if (INV) { t1 = cadd(amc, jb); t3 = csub(amc, jb); }
            else     { t1 = csub(amc, jb); t3 = cadd(amc, jb); }

            const int ob = q + (p << (ls + 2));   // q + s*4p
            y[ob]         = cadd(apc, bpd);
            y[ob +   s]   = cmul(w1, t1);
            y[ob + 2*s]   = cmul(w2, csub(apc, bpd));
            y[ob + 3*s]   = cmul(w3, t3);
        }
        __syncthreads();
        float2* tmp = x; x = y; y = tmp;
        ls += 2;
    }
    // final radix-2 stage (n=2, s=4096); x==b0, y==b1 here (6 swaps)
    #pragma unroll
    for (int idx = tid; idx < 4096; idx += TFFT) {
        const float2 A = x[idx];
        const float2 B = x[idx + 4096];
        y[idx]        = cadd(A, B);
        y[idx + 4096] = csub(A, B);
    }
    __syncthreads();
}

__device__ __forceinline__ void build_twiddles(float2* tw, int tid)
{
    for (int j = tid; j < 2048; j += TFFT) {
        float s, c;
        sincosf(-6.283185307179586f * (float)j * (1.0f / 8192.0f), &s, &c);
        tw[j] = make_float2(c, s);
    }
}

// Unpack helper: given C=FFT(c) of packed sequence, compute half-spectrum pair
// S[j] = E + T, S[N-j] = conj(E - T), where
// E = (C[j]+conj(C[nj]))/2, O = (C[j]-conj(C[nj]))/(2i), T = e^{-i pi j/N} * O.
__device__ __forceinline__ void rfft_pair(float2 Cj, float2 Cn, float cp, float sp,
                                          float2& Sj, float2& Snj)
{
    const float2 E = make_float2(0.5f*(Cj.x + Cn.x), 0.5f*(Cj.y - Cn.y));
    const float2 O = make_float2(0.5f*(Cj.y + Cn.y), -0.5f*(Cj.x - Cn.x));
    const float2 W16 = make_float2(cp, -sp);           // e^{-i pi j / 8192}
    const float2 T = cmul(W16, O);
    Sj  = cadd(E, T);
    const float2 emt = csub(E, T);
    Snj = make_float2(emt.x, -emt.y);
}

// ---------------- kernel A1: MLP layers 1-3 (33 -> 64 -> 64 -> 64, sin activations) ----
__global__ void k_mlp(const float* __restrict__ z, const float* __restrict__ freq,
                      const float* __restrict__ W1, const float* __restrict__ b1,
                      const float* __restrict__ W2, const float* __restrict__ b2,
                      const float* __restrict__ W3, const float* __restrict__ b3)
{
    __shared__ float zs [4][33];
    __shared__ float hs [4][64];
    __shared__ float hs2[4][64];
    const int f = threadIdx.x & 63;
    const int g = threadIdx.x >> 6;
    const int l = blockIdx.x * 4 + g;

    if (f < 33) zs[g][f] = z[l * 33 + f];
    __syncthreads();

    const float fr = freq[f];
    float acc = b1[f];
    #pragma unroll
    for (int e = 0; e < 33; e++) acc = fmaf(zs[g][e], W1[e * 64 + f], acc);
    hs[g][f] = sinf(fr * acc);
    __syncthreads();

    acc = b2[f];
    #pragma unroll
    for (int e = 0; e < 64; e++) acc = fmaf(hs[g][e], W2[e * 64 + f], acc);
    hs2[g][f] = sinf(fr * acc);
    __syncthreads();

    acc = b3[f];
    #pragma unroll
    for (int e = 0; e < 64; e++) acc = fmaf(hs2[g][e], W3[e * 64 + f], acc);
    g_h3[l * 64 + f] = sinf(fr * acc);
}

// ---------------- kernel A2: k[d][l] = (h3[l,:] @ Wout[:,d]) * (exp(-t[l]*|delta[d]|)+0.05)
// Block: 256 threads, tile = 16 l x 768 d. Each thread: 3 d values x 16 l accumulators.
__global__ void k_wout(const float* __restrict__ Wout, const float* __restrict__ t,
                       const float* __restrict__ deltas)
{
    __shared__ float h3s[16 * 64];
    __shared__ float ts[16];
    const int tid = threadIdx.x;
    const int l0 = blockIdx.x * 16;

    for (int i = tid; i < 1024; i += 256) h3s[i] = g_h3[l0 * 64 + i];
    if (tid < 16) ts[tid] = t[l0 + tid];
    __syncthreads();

    float acc[3][16];
    #pragma unroll
    for (int j = 0; j < 3; j++)
        #pragma unroll
        for (int l = 0; l < 16; l++) acc[j][l] = 0.0f;

    #pragma unroll 4
    for (int f = 0; f < 64; f++) {
        const float w0 = Wout[f * 768 + tid];
        const float w1 = Wout[f * 768 + tid + 256];
        const float w2 = Wout[f * 768 + tid + 512];
        #pragma unroll
        for (int l = 0; l < 16; l++) {
            const float h = h3s[l * 64 + f];
            acc[0][l] = fmaf(h, w0, acc[0][l]);
            acc[1][l] = fmaf(h, w1, acc[1][l]);
            acc[2][l] = fmaf(h, w2, acc[2][l]);
        }
    }

    #pragma unroll
    for (int j = 0; j < 3; j++) {
        const int d = tid + j * 256;
        const float ad = fabsf(deltas[d]);
        float v[16];
        #pragma unroll
        for (int l = 0; l < 16; l++)
            v[l] = acc[j][l] * (expf(-ts[l] * ad) + 0.05f);
        float4* dst = (float4*)(g_k + (size_t)d * LSEQ + l0);
        dst[0] = make_float4(v[0],  v[1],  v[2],  v[3]);
        dst[1] = make_float4(v[4],  v[5],  v[6],  v[7]);
        dst[2] = make_float4(v[8],  v[9],  v[10], v[11]);
        dst[3] = make_float4(v[12], v[13], v[14], v[15]);
    }
}

// ---------------- kernel B: Kf[d][j] = rfft(k_d, 16384)[j] / 16384,  j = 0..8192 ---------
__global__ void __launch_bounds__(TFFT) k_kfft()
{
    extern __shared__ float2 smem[];
    float2* b0 = smem;
    float2* b1 = smem + NFFT;
    float2* tw = smem + 2 * NFFT;
    const int tid = threadIdx.x;
    const int d = blockIdx.x;

    build_twiddles(tw, tid);
    const float2* kr = (const float2*)(g_k + (size_t)d * LSEQ);
    // Split load: unconditional in-bounds loads, then zero-fill. No predicated
    // global loads (compiler speculation of a ternary-guarded LDG caused OOB).
    for (int n = tid; n < 4096; n += TFFT)
        b0[n] = kr[n];
    for (int n = 4096 + tid; n < NFFT; n += TFFT)
        b0[n] = make_float2(0.f, 0.f);
    __syncthreads();

    fft8k<0>(b0, b1, tw, tid);

    float2* Kf = g_Kf + (size_t)d * 8200;
    const float sc = 1.0f / 16384.0f;
    for (int j = tid; j <= 4096; j += TFFT) {
        if (j == 0) {
            const float2 C0 = b1[0];
            Kf[0]    = make_float2((C0.x + C0.y) * sc, 0.f);
            Kf[8192] = make_float2((C0.x - C0.y) * sc, 0.f);
        } else {
            const int nj = NFFT - j;
            float sp, cp;
            sincosf(3.14159265358979323846f * (float)j * (1.0f / 8192.0f), &sp, &cp);
            float2 Sj, Snj;
            rfft_pair(b1[j], b1[nj], cp, sp, Sj, Snj);
            Kf[j]  = make_float2(Sj.x * sc,  Sj.y * sc);
            Kf[nj] = make_float2(Snj.x * sc, Snj.y * sc);
        }
    }
}

// ---------------- kernel C: per-row fused rFFT -> multiply -> irFFT -> +D*x -------------
__global__ void __launch_bounds__(TFFT) k_conv(const float* __restrict__ x,
                                               const float* __restrict__ Dv,
                                               float* __restrict__ out)
{
    extern __shared__ float2 smem[];
    float2* b0 = smem;
    float2* b1 = smem + NFFT;
    float2* tw = smem + 2 * NFFT;
    const int tid = threadIdx.x;
    const int row = blockIdx.x;
    const int d = row % DM;

    build_twiddles(tw, tid);
    const float2* x2 = (const float2*)(x + (size_t)row * LSEQ);
    // Split load: unconditional in-bounds loads, then zero-fill (see k_kfft note).
    for (int n = tid; n < 4096; n += TFFT)
        b0[n] = x2[n];
    for (int n = 4096 + tid; n < NFFT; n += TFFT)
        b0[n] = make_float2(0.f, 0.f);
    __syncthreads();

    fft8k<0>(b0, b1, tw, tid);   // C = FFT(packed x), in b1

    // spectral: S = unpack(C); P = S * Kf; G = repack for inverse; write G into b0
    const float2* __restrict__ Kf = g_Kf + (size_t)d * 8200;
    for (int j = tid; j <= 4096; j += TFFT) {
        if (j == 0) {
            const float2 C0 = b1[0];
            const float S0 = C0.x + C0.y;
            const float SN = C0.x - C0.y;
            const float2 K0 = Kf[0];
            const float2 KN = Kf[8192];
            const float2 P0 = make_float2(S0 * K0.x, S0 * K0.y);
            const float2 PN = make_float2(SN * KN.x, SN * KN.y);
            // G0 = (P0 + PN) + i*(P0 - PN)
            const float2 U = cadd(P0, PN);
            const float2 W = csub(P0, PN);
            b0[0] = make_float2(U.x - W.y, U.y + W.x);
        } else {
            const int nj = NFFT - j;
            float sp, cp;
            sincosf(3.14159265358979323846f * (float)j * (1.0f / 8192.0f), &sp, &cp);
            float2 Sj, Snj;
            rfft_pair(b1[j], b1[nj], cp, sp, Sj, Snj);
            const float2 Pj = cmul(Sj,  Kf[j]);
            const float2 Pn = cmul(Snj, Kf[nj]);
            // G[j]  = (Pj + conj(Pn)) + i * V  * (Pj - conj(Pn)),  V  = e^{+i pi j/N} = (cp, sp)
            // G[nj] = (Pn + conj(Pj)) + i * V' * (Pn - conj(Pj)),  V' = (-cp, sp)
            {
                const float2 U  = make_float2(Pj.x + Pn.x, Pj.y - Pn.y);
                const float2 Wd = make_float2(Pj.x - Pn.x, Pj.y + Pn.y);
                const float2 VW = cmul(make_float2(cp, sp), Wd);
                b0[j] = make_float2(U.x - VW.y, U.y + VW.x);
            }
            {
                const float2 U  = make_float2(Pn.x + Pj.x, Pn.y - Pj.y);
                const float2 Wd = make_float2(Pn.x - Pj.x, Pn.y + Pj.y);
                const float2 VW = cmul(make_float2(-cp, sp), Wd);
                b0[nj] = make_float2(U.x - VW.y, U.y + VW.x);
            }
        }
    }
    __syncthreads();

    fft8k<1>(b0, b1, tw, tid);   // z = unscaled IDFT(G), in b1; y[2n]=Re z[n], y[2n+1]=Im z[n]

    const float Dd = Dv[d];
    float2* o2 = (float2*)(out + (size_t)row * LSEQ);
    for (int n = tid; n < 4096; n += TFFT) {
        const float2 zv = b1[n];
        const float2 xv = x2[n];
        o2[n] = make_float2(fmaf(Dd, xv.x, zv.x), fmaf(Dd, xv.y, zv.y));
    }
}

// ---------------- launch ----------------
extern "C" void kernel_launch(void* const* d_in, const int* in_sizes, int n_in,
                              void* d_out, int out_size)
{
    const float* x      = (const float*)d_in[0];
    const float* z      = (const float*)d_in[1];
    const float* t      = (const float*)d_in[2];
    const float* freq   = (const float*)d_in[3];
    const float* W1     = (const float*)d_in[4];
    const float* b1     = (const float*)d_in[5];
    const float* W2     = (const float*)d_in[6];
    const float* b2     = (const float*)d_in[7];
    const float* W3     = (const float*)d_in[8];
    const float* b3     = (const float*)d_in[9];
    const float* Wout   = (const float*)d_in[10];
    const float* deltas = (const float*)d_in[11];
    const float* Dv     = (const float*)d_in[12];
    float* out = (float*)d_out;

    cudaFuncSetAttribute(k_kfft, cudaFuncAttributeMaxDynamicSharedMemorySize, SMEM_BYTES);
    cudaFuncSetAttribute(k_conv, cudaFuncAttributeMaxDynamicSharedMemorySize, SMEM_BYTES);

    k_mlp <<<LSEQ / 4, 256>>>(z, freq, W1, b1, W2, b2, W3, b3);
    k_wout<<<LSEQ / 16, 256>>>(Wout, t, deltas);
    k_kfft<<<DM, TFFT, SMEM_BYTES>>>();
    k_conv<<<BATCH * DM, TFFT, SMEM_BYTES>>>(x, Dv, out);
}

// round 5
// speedup vs baseline: 1.4846x; 1.4846x over previous
#include <cuda_runtime.h>
#include <math.h>
#include <stdint.h>

#define NFFT 8192
#define LSEQ 8192
#define DM   768
#define BATCH 4
#define TFFT 512
#define NB   1024   // butterflies per radix-8 stage = NFFT/8
#define SMEM_BYTES ((NFFT*2 + 2048) * (int)sizeof(float2))  // 147456

// ---------------- scratch (device globals; no runtime allocation) ----------------
__device__ __align__(16) float  g_h3[LSEQ * 64];        // 2 MB
__device__ __align__(16) float  g_k [DM * LSEQ];        // 25 MB, d-major
__device__ __align__(16) float2 g_Kf[DM * 8200];        // 50 MB, half-spectra (0..8192), stride 8200

// ---------------- complex helpers ----------------
__device__ __forceinline__ float2 cmul(float2 a, float2 b) {
    return make_float2(a.x*b.x - a.y*b.y, a.x*b.y + a.y*b.x);
}
__device__ __forceinline__ float2 cadd(float2 a, float2 b) { return make_float2(a.x+b.x, a.y+b.y); }
__device__ __forceinline__ float2 csub(float2 a, float2 b) { return make_float2(a.x-b.x, a.y-b.y); }

// DFT4: c_m = sum_u b_u w^(mu), w = -i (fwd) / +i (inv)
template<int INV>
__device__ __forceinline__ void dft4(float2 b0, float2 b1, float2 b2, float2 b3,
                                     float2& c0, float2& c1, float2& c2, float2& c3)
{
    const float2 apc = cadd(b0, b2), amc = csub(b0, b2);
    const float2 bpd = cadd(b1, b3), bmd = csub(b1, b3);
    c0 = cadd(apc, bpd);
    c2 = csub(apc, bpd);
    if (INV) { c1 = make_float2(amc.x - bmd.y, amc.y + bmd.x);   // amc + i*bmd
               c3 = make_float2(amc.x + bmd.y, amc.y - bmd.x); } // amc - i*bmd
    else     { c1 = make_float2(amc.x + bmd.y, amc.y - bmd.x);   // amc - i*bmd
               c3 = make_float2(amc.x - bmd.y, amc.y + bmd.x); } // amc + i*bmd
}

// DFT8 via even/odd split: Y_m = E_m + w8^m O_m, Y_{m+4} = E_m - w8^m O_m
template<int INV>
__device__ __forceinline__ void dft8(const float2 a[8], float2 Y[8])
{
    float2 E0,E1,E2,E3, O0,O1,O2,O3;
    dft4<INV>(a[0],a[2],a[4],a[6], E0,E1,E2,E3);
    dft4<INV>(a[1],a[3],a[5],a[7], O0,O1,O2,O3);
    const float c = 0.70710678118654752f;
    float2 w1O, w2O, w3O;
    if (INV) {
        w1O = make_float2(c*(O1.x - O1.y),  c*(O1.x + O1.y));   // ( c, c)*O1
        w2O = make_float2(-O2.y, O2.x);                          // (+i)*O2
        w3O = make_float2(-c*(O3.x + O3.y), c*(O3.x - O3.y));   // (-c, c)*O3
    } else {
        w1O = make_float2(c*(O1.x + O1.y),  c*(O1.y - O1.x));   // ( c,-c)*O1
        w2O = make_float2(O2.y, -O2.x);                          // (-i)*O2
        w3O = make_float2(c*(O3.y - O3.x), -c*(O3.x + O3.y));   // (-c,-c)*O3
    }
    Y[0]=cadd(E0,O0);  Y[4]=csub(E0,O0);
    Y[1]=cadd(E1,w1O); Y[5]=csub(E1,w1O);
    Y[2]=cadd(E2,w2O); Y[6]=csub(E2,w2O);
    Y[3]=cadd(E3,w3O); Y[7]=csub(E3,w3O);
}

// General radix-8 Stockham stage (smem -> smem). ls = log2(s).
template<int INV>
__device__ __forceinline__ void stage8(const float2* __restrict__ xin, float2* __restrict__ yout,
                                       const float2* __restrict__ tw, const int ls, const int tid)
{
    #pragma unroll
    for (int it = 0; it < NB / TFFT; it++) {
        const int idx = tid + it * TFFT;
        const int s = 1 << ls;
        const int q = idx & (s - 1);
        const int p = idx >> ls;
        float2 a[8];
        #pragma unroll
        for (int m = 0; m < 8; m++) a[m] = xin[idx + m * NB];
        float2 Y[8];
        dft8<INV>(a, Y);
        float2 w1 = tw[p << ls];
        if (INV) w1.y = -w1.y;
        const float2 w2 = cmul(w1, w1);
        const float2 w3 = cmul(w1, w2);
        const float2 w4 = cmul(w2, w2);
        const float2 w5 = cmul(w2, w3);
        const float2 w6 = cmul(w3, w3);
        const float2 w7 = cmul(w3, w4);
        const int ob = q + (p << (ls + 3));
        yout[ob      ] = Y[0];
        yout[ob +   s] = cmul(w1, Y[1]);
        yout[ob + 2*s] = cmul(w2, Y[2]);
        yout[ob + 3*s] = cmul(w3, Y[3]);
        yout[ob + 4*s] = cmul(w4, Y[4]);
        yout[ob + 5*s] = cmul(w5, Y[5]);
        yout[ob + 6*s] = cmul(w6, Y[6]);
        yout[ob + 7*s] = cmul(w7, Y[7]);
    }
    __syncthreads();
}

// Forward stage 0 (s=1) fused with the gmem load; inputs 4..7 are zero (zero padding).
__device__ __forceinline__ void stage0_fwd_gmem(const float2* __restrict__ g, float2* __restrict__ yout,
                                                const float2* __restrict__ tw, const int tid)
{
    #pragma unroll
    for (int it = 0; it < NB / TFFT; it++) {
        const int idx = tid + it * TFFT;
        const float2 a0 = g[idx];
        const float2 a1 = g[idx + NB];
        const float2 a2 = g[idx + 2*NB];
        const float2 a3 = g[idx + 3*NB];
        // E = DFT4(a0,a2,0,0), O = DFT4(a1,a3,0,0), forward
        const float2 E0 = cadd(a0, a2), E2 = csub(a0, a2);
        const float2 E1 = make_float2(a0.x + a2.y, a0.y - a2.x);  // a0 - i*a2
        const float2 E3 = make_float2(a0.x - a2.y, a0.y + a2.x);  // a0 + i*a2
        const float2 O0 = cadd(a1, a3), O2 = csub(a1, a3);
        const float2 O1 = make_float2(a1.x + a3.y, a1.y - a3.x);
        const float2 O3 = make_float2(a1.x - a3.y, a1.y + a3.x);
        const float c = 0.70710678118654752f;
        const float2 w1O = make_float2(c*(O1.x + O1.y),  c*(O1.y - O1.x));
        const float2 w2O = make_float2(O2.y, -O2.x);
        const float2 w3O = make_float2(c*(O3.y - O3.x), -c*(O3.x + O3.y));
        float2 Y[8];
        Y[0]=cadd(E0,O0);  Y[4]=csub(E0,O0);
        Y[1]=cadd(E1,w1O); Y[5]=csub(E1,w1O);
        Y[2]=cadd(E2,w2O); Y[6]=csub(E2,w2O);
        Y[3]=cadd(E3,w3O); Y[7]=csub(E3,w3O);
        const float2 w1 = tw[idx];           // p = idx, s = 1
        const float2 w2 = cmul(w1, w1);
        const float2 w3 = cmul(w1, w2);
        const float2 w4 = cmul(w2, w2);
        const float2 w5 = cmul(w2, w3);
        const float2 w6 = cmul(w3, w3);
        const float2 w7 = cmul(w3, w4);
        const int ob = idx << 3;
        yout[ob    ] = Y[0];
        yout[ob + 1] = cmul(w1, Y[1]);
        yout[ob + 2] = cmul(w2, Y[2]);
        yout[ob + 3] = cmul(w3, Y[3]);
        yout[ob + 4] = cmul(w4, Y[4]);
        yout[ob + 5] = cmul(w5, Y[5]);
        yout[ob + 6] = cmul(w6, Y[6]);
        yout[ob + 7] = cmul(w7, Y[7]);
    }
    __syncthreads();
}

__device__ __forceinline__ void build_twiddles(float2* tw, int tid)
{
    for (int j = tid; j < 2048; j += TFFT) {
        float s, c;
        sincosf(-6.283185307179586f * (float)j * (1.0f / 8192.0f), &s, &c);
        tw[j] = make_float2(c, s);
    }
    __syncthreads();
}

// Unpack: S[j] = E + T, S[N-j] = conj(E - T); W16 = e^{-i pi j/N} passed in.
__device__ __forceinline__ void rfft_pair(float2 Cj, float2 Cn, float2 W16,
                                          float2& Sj, float2& Snj)
{
    const float2 E = make_float2(0.5f*(Cj.x + Cn.x), 0.5f*(Cj.y - Cn.y));
    const float2 O = make_float2(0.5f*(Cj.y + Cn.y), -0.5f*(Cj.x - Cn.x));
    const float2 T = cmul(W16, O);
    Sj  = cadd(E, T);
    const float2 emt = csub(E, T);
    Snj = make_float2(emt.x, -emt.y);
}

// e^{-i pi/8192}
#define W0X 0.99999992646571789f
#define W0Y (-3.8349518757139556e-4f)

// ---------------- kernel A1: MLP layers 1-3 (33 -> 64 -> 64 -> 64, sin activations) ----
__global__ void k_mlp(const float* __restrict__ z, const float* __restrict__ freq,
                      const float* __restrict__ W1, const float* __restrict__ b1,
                      const float* __restrict__ W2, const float* __restrict__ b2,
                      const float* __restrict__ W3, const float* __restrict__ b3)
{
    __shared__ float zs [4][33];
    __shared__ float hs [4][64];
    __shared__ float hs2[4][64];
    const int f = threadIdx.x & 63;
    const int g = threadIdx.x >> 6;
    const int l = blockIdx.x * 4 + g;

    if (f < 33) zs[g][f] = z[l * 33 + f];
    __syncthreads();

    const float fr = freq[f];
    float acc = b1[f];
    #pragma unroll
    for (int e = 0; e < 33; e++) acc = fmaf(zs[g][e], W1[e * 64 + f], acc);
    hs[g][f] = sinf(fr * acc);
    __syncthreads();

    acc = b2[f];
    #pragma unroll
    for (int e = 0; e < 64; e++) acc = fmaf(hs[g][e], W2[e * 64 + f], acc);
    hs2[g][f] = sinf(fr * acc);
    __syncthreads();

    acc = b3[f];
    #pragma unroll
    for (int e = 0; e < 64; e++) acc = fmaf(hs2[g][e], W3[e * 64 + f], acc);
    g_h3[l * 64 + f] = sinf(fr * acc);
}

// ---------------- kernel A2: k[d][l] = (h3[l,:] @ Wout[:,d]) * (exp(-t[l]*|delta[d]|)+0.05)
__global__ void k_wout(const float* __restrict__ Wout, const float* __restrict__ t,
                       const float* __restrict__ deltas)
{
    __shared__ float h3s[16 * 64];
    __shared__ float ts[16];
    const int tid = threadIdx.x;
    const int l0 = blockIdx.x * 16;

    for (int i = tid; i < 1024; i += 256) h3s[i] = g_h3[l0 * 64 + i];
    if (tid < 16) ts[tid] = t[l0 + tid];
    __syncthreads();

    float acc[3][16];
    #pragma unroll
    for (int j = 0; j < 3; j++)
        #pragma unroll
        for (int l = 0; l < 16; l++) acc[j][l] = 0.0f;

    #pragma unroll 4
    for (int f = 0; f < 64; f++) {
        const float w0 = Wout[f * 768 + tid];
        const float w1 = Wout[f * 768 + tid + 256];
        const float w2 = Wout[f * 768 + tid + 512];
        #pragma unroll
        for (int l = 0; l < 16; l++) {
            const float h = h3s[l * 64 + f];
            acc[0][l] = fmaf(h, w0, acc[0][l]);
            acc[1][l] = fmaf(h, w1, acc[1][l]);
            acc[2][l] = fmaf(h, w2, acc[2][l]);
        }
    }

    #pragma unroll
    for (int j = 0; j < 3; j++) {
        const int d = tid + j * 256;
        const float ad = fabsf(deltas[d]);
        float v[16];
        #pragma unroll
        for (int l = 0; l < 16; l++)
            v[l] = acc[j][l] * (expf(-ts[l] * ad) + 0.05f);
        float4* dst = (float4*)(g_k + (size_t)d * LSEQ + l0);
        dst[0] = make_float4(v[0],  v[1],  v[2],  v[3]);
        dst[1] = make_float4(v[4],  v[5],  v[6],  v[7]);
        dst[2] = make_float4(v[8],  v[9],  v[10], v[11]);
        dst[3] = make_float4(v[12], v[13], v[14], v[15]);
    }
}

// ---------------- kernel B: Kf[d][j] = rfft(k_d, 16384)[j] / 16384,  j = 0..8192 ---------
__global__ void __launch_bounds__(TFFT) k_kfft()
{
    extern __shared__ float2 smem[];
    float2* b0 = smem;
    float2* b1 = smem + NFFT;
    float2* tw = smem + 2 * NFFT;
    const int tid = threadIdx.x;
    const int d = blockIdx.x;

    build_twiddles(tw, tid);
    const float2* kr = (const float2*)(g_k + (size_t)d * LSEQ);

    stage0_fwd_gmem(kr, b1, tw, tid);   // gmem -> b1 (s=1, pruned zeros)
    stage8<0>(b1, b0, tw, 3, tid);
    stage8<0>(b0, b1, tw, 6, tid);
    stage8<0>(b1, b0, tw, 9, tid);
    // pre-final-radix2 data in b0; fuse radix-2 + unpack + store

    float2* Kf = g_Kf + (size_t)d * 8200;
    const float sc = 1.0f / 16384.0f;
    for (int j = tid; j <= 4096; j += TFFT) {
        if (j == 0) {
            const float2 C0 = cadd(b0[0], b0[4096]);
            Kf[0]    = make_float2((C0.x + C0.y) * sc, 0.f);
            Kf[8192] = make_float2((C0.x - C0.y) * sc, 0.f);
        } else if (j == 4096) {
            const float2 Cm = csub(b0[0], b0[4096]);       // C[4096]
            Kf[4096] = make_float2(Cm.x * sc, -Cm.y * sc); // S = (Cx, -Cy)
        } else {
            const int nj = NFFT - j;
            const float2 Cj = cadd(b0[j], b0[j + 4096]);
            const float2 Cn = csub(b0[4096 - j], b0[NFFT - j]);
            float2 W16 = tw[j >> 1];
            if (j & 1) W16 = cmul(W16, make_float2(W0X, W0Y));
            float2 Sj, Snj;
            rfft_pair(Cj, Cn, W16, Sj, Snj);
            Kf[j]  = make_float2(Sj.x * sc,  Sj.y * sc);
            Kf[nj] = make_float2(Snj.x * sc, Snj.y * sc);
        }
    }
}

// ---------------- kernel C: per-row fused rFFT -> multiply -> irFFT -> +D*x -------------
__global__ void __launch_bounds__(TFFT) k_conv(const float* __restrict__ x,
                                               const float* __restrict__ Dv,
                                               float* __restrict__ out)
{
    extern __shared__ float2 smem[];
    float2* b0 = smem;
    float2* b1 = smem + NFFT;
    float2* tw = smem + 2 * NFFT;
    const int tid = threadIdx.x;
    const int row = blockIdx.x;
    const int d = row % DM;

    build_twiddles(tw, tid);
    const float2* x2 = (const float2*)(x + (size_t)row * LSEQ);

    // forward FFT of packed x: stage0 fused with gmem load
    stage0_fwd_gmem(x2, b1, tw, tid);
    stage8<0>(b1, b0, tw, 3, tid);
    stage8<0>(b0, b1, tw, 6, tid);
    stage8<0>(b1, b0, tw, 9, tid);
    // pre-final-radix2 data in b0

    // fused: final fwd radix-2 + unpack + *Kf + repack -> write G to b1
    const float2* __restrict__ Kf = g_Kf + (size_t)d * 8200;
    for (int j = tid; j <= 4096; j += TFFT) {
        if (j == 0) {
            const float2 C0 = cadd(b0[0], b0[4096]);
            const float S0 = C0.x + C0.y;
            const float SN = C0.x - C0.y;
            const float2 K0 = Kf[0];
            const float2 KN = Kf[8192];
            const float2 P0 = make_float2(S0 * K0.x, S0 * K0.y);
            const float2 PN = make_float2(SN * KN.x, SN * KN.y);
            const float2 U = cadd(P0, PN);
            const float2 W = csub(P0, PN);
            b1[0] = make_float2(U.x - W.y, U.y + W.x);
        } else if (j == 4096) {
            const float2 Cm = csub(b0[0], b0[4096]);            // C[4096]
            const float2 S = make_float2(Cm.x, -Cm.y);
            const float2 P = cmul(S, Kf[4096]);
            b1[4096] = make_float2(2.0f * P.x, -2.0f * P.y);
        } else {
            const int nj = NFFT - j;
            const float2 Cj = cadd(b0[j], b0[j + 4096]);
            const float2 Cn = csub(b0[4096 - j], b0[NFFT - j]); // C[nj]
            float2 W16 = tw[j >> 1];
            if (j & 1) W16 = cmul(W16, make_float2(W0X, W0Y));
            float2 Sj, Snj;
            rfft_pair(Cj, Cn, W16, Sj, Snj);
            const float2 Pj = cmul(Sj,  Kf[j]);
            const float2 Pn = cmul(Snj, Kf[nj]);
            // G[j]  = (Pj + conj(Pn)) + i * conj(W16) * (Pj - conj(Pn))
            {
                const float2 U  = make_float2(Pj.x + Pn.x, Pj.y - Pn.y);
                const float2 Wd = make_float2(Pj.x - Pn.x, Pj.y + Pn.y);
                const float2 V  = make_float2(W16.x, -W16.y);
                const float2 VW = cmul(V, Wd);
                b1[j] = make_float2(U.x - VW.y, U.y + VW.x);
            }
            // G[nj] = (Pn + conj(Pj)) + i * (-W16) * (Pn - conj(Pj))
            {
                const float2 U  = make_float2(Pn.x + Pj.x, Pn.y - Pj.y);
                const float2 Wd = make_float2(Pn.x - Pj.x, Pn.y + Pj.y);
                const float2 V  = make_float2(-W16.x, -W16.y);
                const float2 VW = cmul(V, Wd);
                b1[nj] = make_float2(U.x - VW.y, U.y + VW.x);
            }
        }
    }
    __syncthreads();

    // inverse FFT of G (in b1); 4 radix-8 stages, final radix-2 fused with epilogue
    stage8<1>(b1, b0, tw, 0, tid);
    stage8<1>(b0, b1, tw, 3, tid);
    stage8<1>(b1, b0, tw, 6, tid);
    stage8<1>(b0, b1, tw, 9, tid);
    // pre-final-radix2 data in b1; need only z[n] = b1[n] + b1[n+4096], n < 4096

    const float Dd = Dv[d];
    float2* o2 = (float2*)(out + (size_t)row * LSEQ);
    for (int n = tid; n < 4096; n += TFFT) {
        const float2 zv = cadd(b1[n], b1[n + 4096]);
        const float2 xv = x2[n];
        o2[n] = make_float2(fmaf(Dd, xv.x, zv.x), fmaf(Dd, xv.y, zv.y));
    }
}

// ---------------- launch ----------------
extern "C" void kernel_launch(void* const* d_in, const int* in_sizes, int n_in,
                              void* d_out, int out_size)
{
    const float* x      = (const float*)d_in[0];
    const float* z      = (const float*)d_in[1];
    const float* t      = (const float*)d_in[2];
    const float* freq   = (const float*)d_in[3];
    const float* W1     = (const float*)d_in[4];
    const float* b1     = (const float*)d_in[5];
    const float* W2     = (const float*)d_in[6];
    const float* b2     = (const float*)d_in[7];
    const float* W3     = (const float*)d_in[8];
    const float* b3     = (const float*)d_in[9];
    const float* Wout   = (const float*)d_in[10];
    const float* deltas = (const float*)d_in[11];
    const float* Dv     = (const float*)d_in[12];
    float* out = (float*)d_out;

    cudaFuncSetAttribute(k_kfft, cudaFuncAttributeMaxDynamicSharedMemorySize, SMEM_BYTES);
    cudaFuncSetAttribute(k_conv, cudaFuncAttributeMaxDynamicSharedMemorySize, SMEM_BYTES);

    k_mlp <<<LSEQ / 4, 256>>>(z, freq, W1, b1, W2, b2, W3, b3);
    k_wout<<<LSEQ / 16, 256>>>(Wout, t, deltas);
    k_kfft<<<DM, TFFT, SMEM_BYTES>>>();
    k_conv<<<BATCH * DM, TFFT, SMEM_BYTES>>>(x, Dv, out);
}

// round 6
// speedup vs baseline: 1.7904x; 1.2060x over previous
#include <cuda_runtime.h>
#include <math.h>
#include <stdint.h>

#define NFFT 8192
#define LSEQ 8192
#define DM   768
#define BATCH 4
#define TFFT 1024
#define NB   1024   // butterflies per radix-8 stage = NFFT/8
// Padded buffers: one extra float2 per 32 -> kills the 8-way conflict on s=1 writes.
#define PAD(a) ((a) + ((a) >> 5))
#define BUFSZ 8448  // PAD(8191)=8446, round up
#define SMEM_BYTES ((2 * BUFSZ + 2048) * (int)sizeof(float2))  // 151552

// ---------------- scratch (device globals; no runtime allocation) ----------------
__device__ __align__(16) float  g_h3[LSEQ * 64];        // 2 MB
__device__ __align__(16) float  g_k [DM * LSEQ];        // 25 MB, d-major
__device__ __align__(16) float2 g_Kf[DM * 8200];        // 50 MB, half-spectra (0..8192), stride 8200

// ---------------- complex helpers ----------------
__device__ __forceinline__ float2 cmul(float2 a, float2 b) {
    return make_float2(a.x*b.x - a.y*b.y, a.x*b.y + a.y*b.x);
}
__device__ __forceinline__ float2 cadd(float2 a, float2 b) { return make_float2(a.x+b.x, a.y+b.y); }
__device__ __forceinline__ float2 csub(float2 a, float2 b) { return make_float2(a.x-b.x, a.y-b.y); }

// DFT4: c_m = sum_u b_u w^(mu), w = -i (fwd) / +i (inv)
template<int INV>
__device__ __forceinline__ void dft4(float2 b0, float2 b1, float2 b2, float2 b3,
                                     float2& c0, float2& c1, float2& c2, float2& c3)
{
    const float2 apc = cadd(b0, b2), amc = csub(b0, b2);
    const float2 bpd = cadd(b1, b3), bmd = csub(b1, b3);
    c0 = cadd(apc, bpd);
    c2 = csub(apc, bpd);
    if (INV) { c1 = make_float2(amc.x - bmd.y, amc.y + bmd.x);   // amc + i*bmd
               c3 = make_float2(amc.x + bmd.y, amc.y - bmd.x); } // amc - i*bmd
    else     { c1 = make_float2(amc.x + bmd.y, amc.y - bmd.x);   // amc - i*bmd
               c3 = make_float2(amc.x - bmd.y, amc.y + bmd.x); } // amc + i*bmd
}

// DFT8 via even/odd split: Y_m = E_m + w8^m O_m, Y_{m+4} = E_m - w8^m O_m
template<int INV>
__device__ __forceinline__ void dft8(const float2 a[8], float2 Y[8])
{
    float2 E0,E1,E2,E3, O0,O1,O2,O3;
    dft4<INV>(a[0],a[2],a[4],a[6], E0,E1,E2,E3);
    dft4<INV>(a[1],a[3],a[5],a[7], O0,O1,O2,O3);
    const float c = 0.70710678118654752f;
    float2 w1O, w2O, w3O;
    if (INV) {
        w1O = make_float2(c*(O1.x - O1.y),  c*(O1.x + O1.y));   // ( c, c)*O1
        w2O = make_float2(-O2.y, O2.x);                          // (+i)*O2
        w3O = make_float2(-c*(O3.x + O3.y), c*(O3.x - O3.y));   // (-c, c)*O3
    } else {
        w1O = make_float2(c*(O1.x + O1.y),  c*(O1.y - O1.x));   // ( c,-c)*O1
        w2O = make_float2(O2.y, -O2.x);                          // (-i)*O2
        w3O = make_float2(c*(O3.y - O3.x), -c*(O3.x + O3.y));   // (-c,-c)*O3
    }
    Y[0]=cadd(E0,O0);  Y[4]=csub(E0,O0);
    Y[1]=cadd(E1,w1O); Y[5]=csub(E1,w1O);
    Y[2]=cadd(E2,w2O); Y[6]=csub(E2,w2O);
    Y[3]=cadd(E3,w3O); Y[7]=csub(E3,w3O);
}

// General radix-8 Stockham stage (smem -> smem, padded addressing). ls = log2(s).
template<int INV>
__device__ __forceinline__ void stage8(const float2* __restrict__ xin, float2* __restrict__ yout,
                                       const float2* __restrict__ tw, const int ls, const int tid)
{
    #pragma unroll
    for (int it = 0; it < NB / TFFT; it++) {
        const int idx = tid + it * TFFT;
        const int s = 1 << ls;
        const int q = idx & (s - 1);
        const int p = idx >> ls;
        float2 a[8];
        #pragma unroll
        for (int m = 0; m < 8; m++) a[m] = xin[PAD(idx + m * NB)];
        float2 Y[8];
        dft8<INV>(a, Y);
        float2 w1 = tw[p << ls];
        if (INV) w1.y = -w1.y;
        const float2 w2 = cmul(w1, w1);
        const float2 w3 = cmul(w1, w2);
        const float2 w4 = cmul(w2, w2);
        const float2 w5 = cmul(w2, w3);
        const float2 w6 = cmul(w3, w3);
        const float2 w7 = cmul(w3, w4);
        const int ob = q + (p << (ls + 3));
        yout[PAD(ob      )] = Y[0];
        yout[PAD(ob +   s)] = cmul(w1, Y[1]);
        yout[PAD(ob + 2*s)] = cmul(w2, Y[2]);
        yout[PAD(ob + 3*s)] = cmul(w3, Y[3]);
        yout[PAD(ob + 4*s)] = cmul(w4, Y[4]);
        yout[PAD(ob + 5*s)] = cmul(w5, Y[5]);
        yout[PAD(ob + 6*s)] = cmul(w6, Y[6]);
        yout[PAD(ob + 7*s)] = cmul(w7, Y[7]);
    }
    __syncthreads();
}

// Forward stage 0 (s=1) fused with the gmem load; inputs 4..7 are zero (zero padding).
__device__ __forceinline__ void stage0_fwd_gmem(const float2* __restrict__ g, float2* __restrict__ yout,
                                                const float2* __restrict__ tw, const int tid)
{
    #pragma unroll
    for (int it = 0; it < NB / TFFT; it++) {
        const int idx = tid + it * TFFT;
        const float2 a0 = g[idx];
        const float2 a1 = g[idx + NB];
        const float2 a2 = g[idx + 2*NB];
        const float2 a3 = g[idx + 3*NB];
        // E = DFT4(a0,a2,0,0), O = DFT4(a1,a3,0,0), forward
        const float2 E0 = cadd(a0, a2), E2 = csub(a0, a2);
        const float2 E1 = make_float2(a0.x + a2.y, a0.y - a2.x);  // a0 - i*a2
        const float2 E3 = make_float2(a0.x - a2.y, a0.y + a2.x);  // a0 + i*a2
        const float2 O0 = cadd(a1, a3), O2 = csub(a1, a3);
        const float2 O1 = make_float2(a1.x + a3.y, a1.y - a3.x);
        const float2 O3 = make_float2(a1.x - a3.y, a1.y + a3.x);
        const float c = 0.70710678118654752f;
        const float2 w1O = make_float2(c*(O1.x + O1.y),  c*(O1.y - O1.x));
        const float2 w2O = make_float2(O2.y, -O2.x);
        const float2 w3O = make_float2(c*(O3.y - O3.x), -c*(O3.x + O3.y));
        float2 Y[8];
        Y[0]=cadd(E0,O0);  Y[4]=csub(E0,O0);
        Y[1]=cadd(E1,w1O); Y[5]=csub(E1,w1O);
        Y[2]=cadd(E2,w2O); Y[6]=csub(E2,w2O);
        Y[3]=cadd(E3,w3O); Y[7]=csub(E3,w3O);
        const float2 w1 = tw[idx];           // p = idx, s = 1
        const float2 w2 = cmul(w1, w1);
        const float2 w3 = cmul(w1, w2);
        const float2 w4 = cmul(w2, w2);
        const float2 w5 = cmul(w2, w3);
        const float2 w6 = cmul(w3, w3);
        const float2 w7 = cmul(w3, w4);
        const int ob = idx << 3;
        yout[PAD(ob    )] = Y[0];
        yout[PAD(ob + 1)] = cmul(w1, Y[1]);
        yout[PAD(ob + 2)] = cmul(w2, Y[2]);
        yout[PAD(ob + 3)] = cmul(w3, Y[3]);
        yout[PAD(ob + 4)] = cmul(w4, Y[4]);
        yout[PAD(ob + 5)] = cmul(w5, Y[5]);
        yout[PAD(ob + 6)] = cmul(w6, Y[6]);
        yout[PAD(ob + 7)] = cmul(w7, Y[7]);
    }
    __syncthreads();
}

__device__ __forceinline__ void build_twiddles(float2* tw, int tid)
{
    for (int j = tid; j < 2048; j += TFFT) {
        float s, c;
        sincosf(-6.283185307179586f * (float)j * (1.0f / 8192.0f), &s, &c);
        tw[j] = make_float2(c, s);
    }
    __syncthreads();
}

// Unpack: S[j] = E + T, S[N-j] = conj(E - T); W16 = e^{-i pi j/N} passed in.
__device__ __forceinline__ void rfft_pair(float2 Cj, float2 Cn, float2 W16,
                                          float2& Sj, float2& Snj)
{
    const float2 E = make_float2(0.5f*(Cj.x + Cn.x), 0.5f*(Cj.y - Cn.y));
    const float2 O = make_float2(0.5f*(Cj.y + Cn.y), -0.5f*(Cj.x - Cn.x));
    const float2 T = cmul(W16, O);
    Sj  = cadd(E, T);
    const float2 emt = csub(E, T);
    Snj = make_float2(emt.x, -emt.y);
}

// e^{-i pi/8192}
#define W0X 0.99999992646571789f
#define W0Y (-3.8349518757139556e-4f)

// ---------------- kernel A1: MLP layers 1-3 (33 -> 64 -> 64 -> 64, sin activations) ----
__global__ void k_mlp(const float* __restrict__ z, const float* __restrict__ freq,
                      const float* __restrict__ W1, const float* __restrict__ b1,
                      const float* __restrict__ W2, const float* __restrict__ b2,
                      const float* __restrict__ W3, const float* __restrict__ b3)
{
    __shared__ float zs [4][33];
    __shared__ float hs [4][64];
    __shared__ float hs2[4][64];
    const int f = threadIdx.x & 63;
    const int g = threadIdx.x >> 6;
    const int l = blockIdx.x * 4 + g;

    if (f < 33) zs[g][f] = z[l * 33 + f];
    __syncthreads();

    const float fr = freq[f];
    float acc = b1[f];
    #pragma unroll
    for (int e = 0; e < 33; e++) acc = fmaf(zs[g][e], W1[e * 64 + f], acc);
    hs[g][f] = sinf(fr * acc);
    __syncthreads();

    acc = b2[f];
    #pragma unroll
    for (int e = 0; e < 64; e++) acc = fmaf(hs[g][e], W2[e * 64 + f], acc);
    hs2[g][f] = sinf(fr * acc);
    __syncthreads();

    acc = b3[f];
    #pragma unroll
    for (int e = 0; e < 64; e++) acc = fmaf(hs2[g][e], W3[e * 64 + f], acc);
    g_h3[l * 64 + f] = sinf(fr * acc);
}

// ---------------- kernel A2: k[d][l] = (h3[l,:] @ Wout[:,d]) * (exp(-t[l]*|delta[d]|)+0.05)
__global__ void k_wout(const float* __restrict__ Wout, const float* __restrict__ t,
                       const float* __restrict__ deltas)
{
    __shared__ float h3s[16 * 64];
    __shared__ float ts[16];
    const int tid = threadIdx.x;
    const int l0 = blockIdx.x * 16;

    for (int i = tid; i < 1024; i += 256) h3s[i] = g_h3[l0 * 64 + i];
    if (tid < 16) ts[tid] = t[l0 + tid];
    __syncthreads();

    float acc[3][16];
    #pragma unroll
    for (int j = 0; j < 3; j++)
        #pragma unroll
        for (int l = 0; l < 16; l++) acc[j][l] = 0.0f;

    #pragma unroll 4
    for (int f = 0; f < 64; f++) {
        const float w0 = Wout[f * 768 + tid];
        const float w1 = Wout[f * 768 + tid + 256];
        const float w2 = Wout[f * 768 + tid + 512];
        #pragma unroll
        for (int l = 0; l < 16; l++) {
            const float h = h3s[l * 64 + f];
            acc[0][l] = fmaf(h, w0, acc[0][l]);
            acc[1][l] = fmaf(h, w1, acc[1][l]);
            acc[2][l] = fmaf(h, w2, acc[2][l]);
        }
    }

    #pragma unroll
    for (int j = 0; j < 3; j++) {
        const int d = tid + j * 256;
        const float ad = fabsf(deltas[d]);
        float v[16];
        #pragma unroll
        for (int l = 0; l < 16; l++)
            v[l] = acc[j][l] * (expf(-ts[l] * ad) + 0.05f);
        float4* dst = (float4*)(g_k + (size_t)d * LSEQ + l0);
        dst[0] = make_float4(v[0],  v[1],  v[2],  v[3]);
        dst[1] = make_float4(v[4],  v[5],  v[6],  v[7]);
        dst[2] = make_float4(v[8],  v[9],  v[10], v[11]);
        dst[3] = make_float4(v[12], v[13], v[14], v[15]);
    }
}

// ---------------- kernel B: Kf[d][j] = rfft(k_d, 16384)[j] / 16384,  j = 0..8192 ---------
__global__ void __launch_bounds__(TFFT) k_kfft()
{
    extern __shared__ float2 smem[];
    float2* b0 = smem;
    float2* b1 = smem + BUFSZ;
    float2* tw = smem + 2 * BUFSZ;
    const int tid = threadIdx.x;
    const int d = blockIdx.x;

    build_twiddles(tw, tid);
    const float2* kr = (const float2*)(g_k + (size_t)d * LSEQ);

    stage0_fwd_gmem(kr, b1, tw, tid);   // gmem -> b1 (s=1, pruned zeros)
    stage8<0>(b1, b0, tw, 3, tid);
    stage8<0>(b0, b1, tw, 6, tid);
    stage8<0>(b1, b0, tw, 9, tid);
    // pre-final-radix2 data in b0; fuse radix-2 + unpack + store

    float2* Kf = g_Kf + (size_t)d * 8200;
    const float sc = 1.0f / 16384.0f;
    for (int j = tid; j <= 4096; j += TFFT) {
        if (j == 0) {
            const float2 C0 = cadd(b0[PAD(0)], b0[PAD(4096)]);
            Kf[0]    = make_float2((C0.x + C0.y) * sc, 0.f);
            Kf[8192] = make_float2((C0.x - C0.y) * sc, 0.f);
        } else if (j == 4096) {
            const float2 Cm = csub(b0[PAD(0)], b0[PAD(4096)]); // C[4096]
            Kf[4096] = make_float2(Cm.x * sc, -Cm.y * sc);     // S = (Cx, -Cy)
        } else {
            const int nj = NFFT - j;
            const float2 Cj = cadd(b0[PAD(j)], b0[PAD(j + 4096)]);
            const float2 Cn = csub(b0[PAD(4096 - j)], b0[PAD(NFFT - j)]);
            float2 W16 = tw[j >> 1];
            if (j & 1) W16 = cmul(W16, make_float2(W0X, W0Y));
            float2 Sj, Snj;
            rfft_pair(Cj, Cn, W16, Sj, Snj);
            Kf[j]  = make_float2(Sj.x * sc,  Sj.y * sc);
            Kf[nj] = make_float2(Snj.x * sc, Snj.y * sc);
        }
    }
}

// ---------------- kernel C: per-row fused rFFT -> multiply -> irFFT -> +D*x -------------
__global__ void __launch_bounds__(TFFT) k_conv(const float* __restrict__ x,
                                               const float* __restrict__ Dv,
                                               float* __restrict__ out)
{
    extern __shared__ float2 smem[];
    float2* b0 = smem;
    float2* b1 = smem + BUFSZ;
    float2* tw = smem + 2 * BUFSZ;
    const int tid = threadIdx.x;
    const int row = blockIdx.x;
    const int d = row % DM;

    build_twiddles(tw, tid);
    const float2* x2 = (const float2*)(x + (size_t)row * LSEQ);

    // forward FFT of packed x: stage0 fused with gmem load
    stage0_fwd_gmem(x2, b1, tw, tid);
    stage8<0>(b1, b0, tw, 3, tid);
    stage8<0>(b0, b1, tw, 6, tid);
    stage8<0>(b1, b0, tw, 9, tid);
    // pre-final-radix2 data in b0

    // fused: final fwd radix-2 + unpack + *Kf + repack -> write G to b1
    const float2* __restrict__ Kf = g_Kf + (size_t)d * 8200;
    for (int j = tid; j <= 4096; j += TFFT) {
        if (j == 0) {
            const float2 C0 = cadd(b0[PAD(0)], b0[PAD(4096)]);
            const float S0 = C0.x + C0.y;
            const float SN = C0.x - C0.y;
            const float2 K0 = Kf[0];
            const float2 KN = Kf[8192];
            const float2 P0 = make_float2(S0 * K0.x, S0 * K0.y);
            const float2 PN = make_float2(SN * KN.x, SN * KN.y);
            const float2 U = cadd(P0, PN);
            const float2 W = csub(P0, PN);
            b1[PAD(0)] = make_float2(U.x - W.y, U.y + W.x);
        } else if (j == 4096) {
            const float2 Cm = csub(b0[PAD(0)], b0[PAD(4096)]);  // C[4096]
            const float2 S = make_float2(Cm.x, -Cm.y);
            const float2 P = cmul(S, Kf[4096]);
            b1[PAD(4096)] = make_float2(2.0f * P.x, -2.0f * P.y);
        } else {
            const int nj = NFFT - j;
            const float2 Cj = cadd(b0[PAD(j)], b0[PAD(j + 4096)]);
            const float2 Cn = csub(b0[PAD(4096 - j)], b0[PAD(NFFT - j)]); // C[nj]
            float2 W16 = tw[j >> 1];
            if (j & 1) W16 = cmul(W16, make_float2(W0X, W0Y));
            float2 Sj, Snj;
            rfft_pair(Cj, Cn, W16, Sj, Snj);
            const float2 Pj = cmul(Sj,  Kf[j]);
            const float2 Pn = cmul(Snj, Kf[nj]);
            // G[j]  = (Pj + conj(Pn)) + i * conj(W16) * (Pj - conj(Pn))
            {
                const float2 U  = make_float2(Pj.x + Pn.x, Pj.y - Pn.y);
                const float2 Wd = make_float2(Pj.x - Pn.x, Pj.y + Pn.y);
                const float2 V  = make_float2(W16.x, -W16.y);
                const float2 VW = cmul(V, Wd);
                b1[PAD(j)] = make_float2(U.x - VW.y, U.y + VW.x);
            }
            // G[nj] = (Pn + conj(Pj)) + i * (-W16) * (Pn - conj(Pj))
            {
                const float2 U  = make_float2(Pn.x + Pj.x, Pn.y - Pj.y);
                const float2 Wd = make_float2(Pn.x - Pj.x, Pn.y + Pj.y);
                const float2 V  = make_float2(-W16.x, -W16.y);
                const float2 VW = cmul(V, Wd);
                b1[PAD(nj)] = make_float2(U.x - VW.y, U.y + VW.x);
            }
        }
    }
    __syncthreads();

    // inverse FFT of G (in b1); 4 radix-8 stages, final radix-2 fused with epilogue
    stage8<1>(b1, b0, tw, 0, tid);
    stage8<1>(b0, b1, tw, 3, tid);
    stage8<1>(b1, b0, tw, 6, tid);
    stage8<1>(b0, b1, tw, 9, tid);
    // pre-final-radix2 data in b1; need only z[n] = b1[n] + b1[n+4096], n < 4096

    const float Dd = Dv[d];
    float2* o2 = (float2*)(out + (size_t)row * LSEQ);
    for (int n = tid; n < 4096; n += TFFT) {
        const float2 zv = cadd(b1[PAD(n)], b1[PAD(n + 4096)]);
        const float2 xv = x2[n];
        o2[n] = make_float2(fmaf(Dd, xv.x, zv.x), fmaf(Dd, xv.y, zv.y));
    }
}

// ---------------- launch ----------------
extern "C" void kernel_launch(void* const* d_in, const int* in_sizes, int n_in,
                              void* d_out, int out_size)
{
    const float* x      = (const float*)d_in[0];
    const float* z      = (const float*)d_in[1];
    const float* t      = (const float*)d_in[2];
    const float* freq   = (const float*)d_in[3];
    const float* W1     = (const float*)d_in[4];
    const float* b1     = (const float*)d_in[5];
    const float* W2     = (const float*)d_in[6];
    const float* b2     = (const float*)d_in[7];
    const float* W3     = (const float*)d_in[8];
    const float* b3     = (const float*)d_in[9];
    const float* Wout   = (const float*)d_in[10];
    const float* deltas = (const float*)d_in[11];
    const float* Dv     = (const float*)d_in[12];
    float* out = (float*)d_out;

    cudaFuncSetAttribute(k_kfft, cudaFuncAttributeMaxDynamicSharedMemorySize, SMEM_BYTES);
    cudaFuncSetAttribute(k_conv, cudaFuncAttributeMaxDynamicSharedMemorySize, SMEM_BYTES);

    k_mlp <<<LSEQ / 4, 256>>>(z, freq, W1, b1, W2, b2, W3, b3);
    k_wout<<<LSEQ / 16, 256>>>(Wout, t, deltas);
    k_kfft<<<DM, TFFT, SMEM_BYTES>>>();
    k_conv<<<BATCH * DM, TFFT, SMEM_BYTES>>>(x, Dv, out);
}

// round 7
// speedup vs baseline: 1.8002x; 1.0054x over previous
#include <cuda_runtime.h>
#include <math.h>
#include <stdint.h>

#define NFFT 8192
#define LSEQ 8192
#define DM   768
#define BATCH 4
#define TFFT 1024
#define NB   1024   // butterflies per radix-8 stage = NFFT/8
// Padded buffers: one extra float2 per 32 -> kills the 8-way conflict on s=1 writes.
#define PAD(a) ((a) + ((a) >> 5))
// Strength-reduced padded offset for a stride that is a multiple-of-32-safe step:
// PAD(base + OFF) == PAD(base) + WOFF(OFF) for all our stage geometries (verified per LS).
#define WOFF(off) ((off) + ((off) >> 5))
#define BUFSZ 8448  // PAD(8191)=8446, round up
#define SMEM_BYTES ((2 * BUFSZ + 2048) * (int)sizeof(float2))  // 151552

// ---------------- scratch (device globals; no runtime allocation) ----------------
__device__ __align__(16) float  g_h3[LSEQ * 64];        // 2 MB
__device__ __align__(16) float  g_k [DM * LSEQ];        // 25 MB, d-major
__device__ __align__(16) float2 g_Kf[DM * 8200];        // 50 MB, half-spectra (0..8192), stride 8200

// ---------------- packed f32x2 helpers (sm_100a Blackwell) ----------------
__device__ __forceinline__ float2 padd(float2 a, float2 b) {
    float2 r;
    asm("{\n\t"
        ".reg .b64 pa, pb, pc;\n\t"
        "mov.b64 pa, {%2, %3};\n\t"
        "mov.b64 pb, {%4, %5};\n\t"
        "add.rn.f32x2 pc, pa, pb;\n\t"
        "mov.b64 {%0, %1}, pc;\n\t"
        "}"
        : "=f"(r.x), "=f"(r.y)
        : "f"(a.x), "f"(a.y), "f"(b.x), "f"(b.y));
    return r;
}
__device__ __forceinline__ float2 psub(float2 a, float2 b) {
    float2 r;
    asm("{\n\t"
        ".reg .b64 pa, pb, pc;\n\t"
        "mov.b64 pa, {%2, %3};\n\t"
        "mov.b64 pb, {%4, %5};\n\t"
        "sub.rn.f32x2 pc, pa, pb;\n\t"
        "mov.b64 {%0, %1}, pc;\n\t"
        "}"
        : "=f"(r.x), "=f"(r.y)
        : "f"(a.x), "f"(a.y), "f"(b.x), "f"(b.y));
    return r;
}

// ---------------- complex helpers ----------------
__device__ __forceinline__ float2 cmul(float2 a, float2 b) {
    return make_float2(a.x*b.x - a.y*b.y, a.x*b.y + a.y*b.x);
}

// DFT4 (packed): c_m = sum_u b_u w^(mu), w = -i (fwd) / +i (inv)
template<int INV>
__device__ __forceinline__ void dft4p(float2 b0, float2 b1, float2 b2, float2 b3,
                                      float2& c0, float2& c1, float2& c2, float2& c3)
{
    const float2 apc = padd(b0, b2), amc = psub(b0, b2);
    const float2 bpd = padd(b1, b3), bmd = psub(b1, b3);
    c0 = padd(apc, bpd);
    c2 = psub(apc, bpd);
    const float2 ib = make_float2(-bmd.y, bmd.x);  // i * bmd
    if (INV) { c1 = padd(amc, ib); c3 = psub(amc, ib); }
    else     { c1 = psub(amc, ib); c3 = padd(amc, ib); }
}

// DFT8 via even/odd split: Y_m = E_m + w8^m O_m, Y_{m+4} = E_m - w8^m O_m
template<int INV>
__device__ __forceinline__ void dft8(const float2 a[8], float2 Y[8])
{
    float2 E0,E1,E2,E3, O0,O1,O2,O3;
    dft4p<INV>(a[0],a[2],a[4],a[6], E0,E1,E2,E3);
    dft4p<INV>(a[1],a[3],a[5],a[7], O0,O1,O2,O3);
    const float c = 0.70710678118654752f;
    float2 w1O, w2O, w3O;
    if (INV) {
        w1O = make_float2(c*(O1.x - O1.y),  c*(O1.x + O1.y));   // ( c, c)*O1
        w2O = make_float2(-O2.y, O2.x);                          // (+i)*O2
        w3O = make_float2(-c*(O3.x + O3.y), c*(O3.x - O3.y));   // (-c, c)*O3
    } else {
        w1O = make_float2(c*(O1.x + O1.y),  c*(O1.y - O1.x));   // ( c,-c)*O1
        w2O = make_float2(O2.y, -O2.x);                          // (-i)*O2
        w3O = make_float2(c*(O3.y - O3.x), -c*(O3.x + O3.y));   // (-c,-c)*O3
    }
    Y[0]=padd(E0,O0);  Y[4]=psub(E0,O0);
    Y[1]=padd(E1,w1O); Y[5]=psub(E1,w1O);
    Y[2]=padd(E2,w2O); Y[6]=psub(E2,w2O);
    Y[3]=padd(E3,w3O); Y[7]=psub(E3,w3O);
}

// General radix-8 Stockham stage (smem -> smem, padded addressing, compile-time LS).
template<int INV, int LS>
__device__ __forceinline__ void stage8(const float2* __restrict__ xin, float2* __restrict__ yout,
                                       const float2* __restrict__ tw, const int tid)
{
    const int S = 1 << LS;
    const int idx = tid;                 // TFFT == NB: exactly one butterfly per thread
    const int q = idx & (S - 1);
    const int p = idx >> LS;
    const int rb = PAD(idx);             // strength-reduced: reads at rb + WOFF(m*NB)
    float2 a[8];
    #pragma unroll
    for (int m = 0; m < 8; m++) a[m] = xin[rb + WOFF(m * NB)];
    float2 Y[8];
    dft8<INV>(a, Y);
    float2 w1 = tw[p << LS];
    if (INV) w1.y = -w1.y;
    const float2 w2 = cmul(w1, w1);
    const float2 w3 = cmul(w1, w2);
    const float2 w4 = cmul(w2, w2);
    const float2 w5 = cmul(w2, w3);
    const float2 w6 = cmul(w3, w3);
    const float2 w7 = cmul(w3, w4);
    const int ob = q + (p << (LS + 3));
    const int wb = PAD(ob);              // strength-reduced: writes at wb + WOFF(m*S)
    yout[wb + WOFF(0 * S)] = Y[0];
    yout[wb + WOFF(1 * S)] = cmul(w1, Y[1]);
    yout[wb + WOFF(2 * S)] = cmul(w2, Y[2]);
    yout[wb + WOFF(3 * S)] = cmul(w3, Y[3]);
    yout[wb + WOFF(4 * S)] = cmul(w4, Y[4]);
    yout[wb + WOFF(5 * S)] = cmul(w5, Y[5]);
    yout[wb + WOFF(6 * S)] = cmul(w6, Y[6]);
    yout[wb + WOFF(7 * S)] = cmul(w7, Y[7]);
    __syncthreads();
}

// Forward stage 0 (s=1) fused with the gmem load; inputs 4..7 are zero (zero padding).
__device__ __forceinline__ void stage0_fwd_gmem(const float2* __restrict__ g, float2* __restrict__ yout,
                                                const float2* __restrict__ tw, const int tid)
{
    const int idx = tid;
    const float2 a0 = g[idx];
    const float2 a1 = g[idx + NB];
    const float2 a2 = g[idx + 2*NB];
    const float2 a3 = g[idx + 3*NB];
    // E = DFT4(a0,a2,0,0), O = DFT4(a1,a3,0,0), forward
    const float2 E0 = padd(a0, a2), E2 = psub(a0, a2);
    const float2 ia2 = make_float2(-a2.y, a2.x);
    const float2 E1 = psub(a0, ia2);  // a0 - i*a2
    const float2 E3 = padd(a0, ia2);  // a0 + i*a2
    const float2 O0 = padd(a1, a3), O2 = psub(a1, a3);
    const float2 ia3 = make_float2(-a3.y, a3.x);
    const float2 O1 = psub(a1, ia3);
    const float2 O3 = padd(a1, ia3);
    const float c = 0.70710678118654752f;
    const float2 w1O = make_float2(c*(O1.x + O1.y),  c*(O1.y - O1.x));
    const float2 w2O = make_float2(O2.y, -O2.x);
    const float2 w3O = make_float2(c*(O3.y - O3.x), -c*(O3.x + O3.y));
    float2 Y[8];
    Y[0]=padd(E0,O0);  Y[4]=psub(E0,O0);
    Y[1]=padd(E1,w1O); Y[5]=psub(E1,w1O);
    Y[2]=padd(E2,w2O); Y[6]=psub(E2,w2O);
    Y[3]=padd(E3,w3O); Y[7]=psub(E3,w3O);
    const float2 w1 = tw[idx];           // p = idx, s = 1
    const float2 w2 = cmul(w1, w1);
    const float2 w3 = cmul(w1, w2);
    const float2 w4 = cmul(w2, w2);
    const float2 w5 = cmul(w2, w3);
    const float2 w6 = cmul(w3, w3);
    const float2 w7 = cmul(w3, w4);
    const int wb = PAD(idx << 3);        // LS=0: offsets m (m<8 never carries past bit 5)
    yout[wb + 0] = Y[0];
    yout[wb + 1] = cmul(w1, Y[1]);
    yout[wb + 2] = cmul(w2, Y[2]);
    yout[wb + 3] = cmul(w3, Y[3]);
    yout[wb + 4] = cmul(w4, Y[4]);
    yout[wb + 5] = cmul(w5, Y[5]);
    yout[wb + 6] = cmul(w6, Y[6]);
    yout[wb + 7] = cmul(w7, Y[7]);
    __syncthreads();
}

__device__ __forceinline__ void build_twiddles(float2* tw, int tid)
{
    for (int j = tid; j < 2048; j += TFFT) {
        float s, c;
        sincosf(-6.283185307179586f * (float)j * (1.0f / 8192.0f), &s, &c);
        tw[j] = make_float2(c, s);
    }
    __syncthreads();
}

// Unpack: S[j] = E + T, S[N-j] = conj(E - T); W16 = e^{-i pi j/N} passed in.
__device__ __forceinline__ void rfft_pair(float2 Cj, float2 Cn, float2 W16,
                                          float2& Sj, float2& Snj)
{
    const float2 E = make_float2(0.5f*(Cj.x + Cn.x), 0.5f*(Cj.y - Cn.y));
    const float2 O = make_float2(0.5f*(Cj.y + Cn.y), -0.5f*(Cj.x - Cn.x));
    const float2 T = cmul(W16, O);
    Sj  = padd(E, T);
    const float2 emt = psub(E, T);
    Snj = make_float2(emt.x, -emt.y);
}

// e^{-i pi/8192}
#define W0X 0.99999992646571789f
#define W0Y (-3.8349518757139556e-4f)

// ---------------- kernel A1: MLP layers 1-3 (33 -> 64 -> 64 -> 64, sin activations) ----
__global__ void k_mlp(const float* __restrict__ z, const float* __restrict__ freq,
                      const float* __restrict__ W1, const float* __restrict__ b1,
                      const float* __restrict__ W2, const float* __restrict__ b2,
                      const float* __restrict__ W3, const float* __restrict__ b3)
{
    __shared__ float zs [4][33];
    __shared__ float hs [4][64];
    __shared__ float hs2[4][64];
    const int f = threadIdx.x & 63;
    const int g = threadIdx.x >> 6;
    const int l = blockIdx.x * 4 + g;

    if (f < 33) zs[g][f] = z[l * 33 + f];
    __syncthreads();

    const float fr = freq[f];
    float acc = b1[f];
    #pragma unroll
    for (int e = 0; e < 33; e++) acc = fmaf(zs[g][e], W1[e * 64 + f], acc);
    hs[g][f] = sinf(fr * acc);
    __syncthreads();

    acc = b2[f];
    #pragma unroll
    for (int e = 0; e < 64; e++) acc = fmaf(hs[g][e], W2[e * 64 + f], acc);
    hs2[g][f] = sinf(fr * acc);
    __syncthreads();

    acc = b3[f];
    #pragma unroll
    for (int e = 0; e < 64; e++) acc = fmaf(hs2[g][e], W3[e * 64 + f], acc);
    g_h3[l * 64 + f] = sinf(fr * acc);
}

// ---------------- kernel A2: k[d][l] = (h3[l,:] @ Wout[:,d]) * (exp(-t[l]*|delta[d]|)+0.05)
__global__ void k_wout(const float* __restrict__ Wout, const float* __restrict__ t,
                       const float* __restrict__ deltas)
{
    __shared__ float h3s[16 * 64];
    __shared__ float ts[16];
    const int tid = threadIdx.x;
    const int l0 = blockIdx.x * 16;

    for (int i = tid; i < 1024; i += 256) h3s[i] = g_h3[l0 * 64 + i];
    if (tid < 16) ts[tid] = t[l0 + tid];
    __syncthreads();

    float acc[3][16];
    #pragma unroll
    for (int j = 0; j < 3; j++)
        #pragma unroll
        for (int l = 0; l < 16; l++) acc[j][l] = 0.0f;

    #pragma unroll 4
    for (int f = 0; f < 64; f++) {
        const float w0 = Wout[f * 768 + tid];
        const float w1 = Wout[f * 768 + tid + 256];
        const float w2 = Wout[f * 768 + tid + 512];
        #pragma unroll
        for (int l = 0; l < 16; l++) {
            const float h = h3s[l * 64 + f];
            acc[0][l] = fmaf(h, w0, acc[0][l]);
            acc[1][l] = fmaf(h, w1, acc[1][l]);
            acc[2][l] = fmaf(h, w2, acc[2][l]);
        }
    }

    #pragma unroll
    for (int j = 0; j < 3; j++) {
        const int d = tid + j * 256;
        const float ad = fabsf(deltas[d]);
        float v[16];
        #pragma unroll
        for (int l = 0; l < 16; l++)
            v[l] = acc[j][l] * (expf(-ts[l] * ad) + 0.05f);
        float4* dst = (float4*)(g_k + (size_t)d * LSEQ + l0);
        dst[0] = make_float4(v[0],  v[1],  v[2],  v[3]);
        dst[1] = make_float4(v[4],  v[5],  v[6],  v[7]);
        dst[2] = make_float4(v[8],  v[9],  v[10], v[11]);
        dst[3] = make_float4(v[12], v[13], v[14], v[15]);
    }
}

// ---------------- kernel B: Kf[d][j] = rfft(k_d, 16384)[j] / 16384,  j = 0..8192 ---------
__global__ void __launch_bounds__(TFFT) k_kfft()
{
    extern __shared__ float2 smem[];
    float2* b0 = smem;
    float2* b1 = smem + BUFSZ;
    float2* tw = smem + 2 * BUFSZ;
    const int tid = threadIdx.x;
    const int d = blockIdx.x;

    build_twiddles(tw, tid);
    const float2* kr = (const float2*)(g_k + (size_t)d * LSEQ);

    stage0_fwd_gmem(kr, b1, tw, tid);   // gmem -> b1 (s=1, pruned zeros)
    stage8<0, 3>(b1, b0, tw, tid);
    stage8<0, 6>(b0, b1, tw, tid);
    stage8<0, 9>(b1, b0, tw, tid);
    // pre-final-radix2 data in b0; fuse radix-2 + unpack + store

    float2* Kf = g_Kf + (size_t)d * 8200;
    const float sc = 1.0f / 16384.0f;
    for (int j = tid; j <= 4096; j += TFFT) {
        if (j == 0) {
            const float2 C0 = padd(b0[PAD(0)], b0[PAD(4096)]);
            Kf[0]    = make_float2((C0.x + C0.y) * sc, 0.f);
            Kf[8192] = make_float2((C0.x - C0.y) * sc, 0.f);
        } else if (j == 4096) {
            const float2 Cm = psub(b0[PAD(0)], b0[PAD(4096)]); // C[4096]
            Kf[4096] = make_float2(Cm.x * sc, -Cm.y * sc);     // S = (Cx, -Cy)
        } else {
            const int nj = NFFT - j;
            const int pj = PAD(j);
            const int pm = PAD(4096 - j);
            const float2 Cj = padd(b0[pj], b0[pj + WOFF(4096)]);
            const float2 Cn = psub(b0[pm], b0[pm + WOFF(4096)]);
            float2 W16 = tw[j >> 1];
            if (j & 1) W16 = cmul(W16, make_float2(W0X, W0Y));
            float2 Sj, Snj;
            rfft_pair(Cj, Cn, W16, Sj, Snj);
            Kf[j]  = make_float2(Sj.x * sc,  Sj.y * sc);
            Kf[nj] = make_float2(Snj.x * sc, Snj.y * sc);
        }
    }
}

// ---------------- kernel C: per-row fused rFFT -> multiply -> irFFT -> +D*x -------------
__global__ void __launch_bounds__(TFFT) k_conv(const float* __restrict__ x,
                                               const float* __restrict__ Dv,
                                               float* __restrict__ out)
{
    extern __shared__ float2 smem[];
    float2* b0 = smem;
    float2* b1 = smem + BUFSZ;
    float2* tw = smem + 2 * BUFSZ;
    const int tid = threadIdx.x;
    const int row = blockIdx.x;
    const int d = row % DM;

    build_twiddles(tw, tid);
    const float2* x2 = (const float2*)(x + (size_t)row * LSEQ);

    // forward FFT of packed x: stage0 fused with gmem load
    stage0_fwd_gmem(x2, b1, tw, tid);
    stage8<0, 3>(b1, b0, tw, tid);
    stage8<0, 6>(b0, b1, tw, tid);
    stage8<0, 9>(b1, b0, tw, tid);
    // pre-final-radix2 data in b0

    // fused: final fwd radix-2 + unpack + *Kf + repack -> write G to b1
    const float2* __restrict__ Kf = g_Kf + (size_t)d * 8200;
    for (int j = tid; j <= 4096; j += TFFT) {
        if (j == 0) {
            const float2 C0 = padd(b0[PAD(0)], b0[PAD(4096)]);
            const float S0 = C0.x + C0.y;
            const float SN = C0.x - C0.y;
            const float2 K0 = Kf[0];
            const float2 KN = Kf[8192];
            const float2 P0 = make_float2(S0 * K0.x, S0 * K0.y);
            const float2 PN = make_float2(SN * KN.x, SN * KN.y);
            const float2 U = padd(P0, PN);
            const float2 W = psub(P0, PN);
            b1[PAD(0)] = make_float2(U.x - W.y, U.y + W.x);
        } else if (j == 4096) {
            const float2 Cm = psub(b0[PAD(0)], b0[PAD(4096)]);  // C[4096]
            const float2 S = make_float2(Cm.x, -Cm.y);
            const float2 P = cmul(S, Kf[4096]);
            b1[PAD(4096)] = make_float2(2.0f * P.x, -2.0f * P.y);
        } else {
            const int nj = NFFT - j;
            const int pj = PAD(j);
            const int pm = PAD(4096 - j);
            const float2 Cj = padd(b0[pj], b0[pj + WOFF(4096)]);
            const float2 Cn = psub(b0[pm], b0[pm + WOFF(4096)]); // C[nj]
            float2 W16 = tw[j >> 1];
            if (j & 1) W16 = cmul(W16, make_float2(W0X, W0Y));
            float2 Sj, Snj;
            rfft_pair(Cj, Cn, W16, Sj, Snj);
            const float2 Pj = cmul(Sj,  Kf[j]);
            const float2 Pn = cmul(Snj, Kf[nj]);
            // G[j]  = (Pj + conj(Pn)) + i * conj(W16) * (Pj - conj(Pn))
            {
                const float2 U  = make_float2(Pj.x + Pn.x, Pj.y - Pn.y);
                const float2 Wd = make_float2(Pj.x - Pn.x, Pj.y + Pn.y);
                const float2 V  = make_float2(W16.x, -W16.y);
                const float2 VW = cmul(V, Wd);
                b1[pj] = make_float2(U.x - VW.y, U.y + VW.x);
            }
            // G[nj] = (Pn + conj(Pj)) + i * (-W16) * (Pn - conj(Pj))
            {
                const float2 U  = make_float2(Pn.x + Pj.x, Pn.y - Pj.y);
                const float2 Wd = make_float2(Pn.x - Pj.x, Pn.y + Pj.y);
                const float2 V  = make_float2(-W16.x, -W16.y);
                const float2 VW = cmul(V, Wd);
                b1[PAD(nj)] = make_float2(U.x - VW.y, U.y + VW.x);
            }
        }
    }
    __syncthreads();

    // inverse FFT of G (in b1); 4 radix-8 stages, final radix-2 fused with epilogue
    stage8<1, 0>(b1, b0, tw, tid);
    stage8<1, 3>(b0, b1, tw, tid);
    stage8<1, 6>(b1, b0, tw, tid);
    stage8<1, 9>(b0, b1, tw, tid);
    // pre-final-radix2 data in b1; need only z[n] = b1[n] + b1[n+4096], n < 4096

    const float Dd = Dv[d];
    float2* o2 = (float2*)(out + (size_t)row * LSEQ);
    for (int n = tid; n < 4096; n += TFFT) {
        const int pn = PAD(n);
        const float2 zv = padd(b1[pn], b1[pn + WOFF(4096)]);
        const float2 xv = x2[n];
        o2[n] = make_float2(fmaf(Dd, xv.x, zv.x), fmaf(Dd, xv.y, zv.y));
    }
}

// ---------------- launch ----------------
extern "C" void kernel_launch(void* const* d_in, const int* in_sizes, int n_in,
                              void* d_out, int out_size)
{
    const float* x      = (const float*)d_in[0];
    const float* z      = (const float*)d_in[1];
    const float* t      = (const float*)d_in[2];
    const float* freq   = (const float*)d_in[3];
    const float* W1     = (const float*)d_in[4];
    const float* b1     = (const float*)d_in[5];
    const float* W2     = (const float*)d_in[6];
    const float* b2     = (const float*)d_in[7];
    const float* W3     = (const float*)d_in[8];
    const float* b3     = (const float*)d_in[9];
    const float* Wout   = (const float*)d_in[10];
    const float* deltas = (const float*)d_in[11];
    const float* Dv     = (const float*)d_in[12];
    float* out = (float*)d_out;

    cudaFuncSetAttribute(k_kfft, cudaFuncAttributeMaxDynamicSharedMemorySize, SMEM_BYTES);
    cudaFuncSetAttribute(k_conv, cudaFuncAttributeMaxDynamicSharedMemorySize, SMEM_BYTES);

    k_mlp <<<LSEQ / 4, 256>>>(z, freq, W1, b1, W2, b2, W3, b3);
    k_wout<<<LSEQ / 16, 256>>>(Wout, t, deltas);
    k_kfft<<<DM, TFFT, SMEM_BYTES>>>();
    k_conv<<<BATCH * DM, TFFT, SMEM_BYTES>>>(x, Dv, out);
}

// round 8
// speedup vs baseline: 1.9433x; 1.0795x over previous
#include <cuda_runtime.h>
#include <math.h>
#include <stdint.h>

#define NFFT 8192
#define LSEQ 8192
#define DM   768
#define BATCH 4
#define TFFT 1024
// In-place buffer pad: breaks stride-1024/128/16 conflicts; all FFT stages <=2-way.
#define PAD(a) ((a) + ((a) >> 4) + ((a) >> 9))
#define BUFSZ 8720   // PAD(8191)=8717
#define TWSZ  1026   // need tw[0..1024]
#define SMEM_BYTES ((BUFSZ + TWSZ) * (int)sizeof(float2))  // 77968

// ---------------- scratch (device globals; no runtime allocation) ----------------
__device__ __align__(16) float  g_h3[LSEQ * 64];
__device__ __align__(16) float  g_k [DM * LSEQ];
__device__ __align__(16) float2 g_Kf[DM * 8200];   // half-spectra 0..8192, stride 8200

// ---------------- packed f32x2 helpers ----------------
__device__ __forceinline__ float2 padd(float2 a, float2 b) {
    float2 r;
    asm("{\n\t.reg .b64 pa, pb, pc;\n\t"
        "mov.b64 pa, {%2, %3};\n\tmov.b64 pb, {%4, %5};\n\t"
        "add.rn.f32x2 pc, pa, pb;\n\tmov.b64 {%0, %1}, pc;\n\t}"
        : "=f"(r.x), "=f"(r.y) : "f"(a.x), "f"(a.y), "f"(b.x), "f"(b.y));
    return r;
}
__device__ __forceinline__ float2 psub(float2 a, float2 b) {
    float2 r;
    asm("{\n\t.reg .b64 pa, pb, pc;\n\t"
        "mov.b64 pa, {%2, %3};\n\tmov.b64 pb, {%4, %5};\n\t"
        "sub.rn.f32x2 pc, pa, pb;\n\tmov.b64 {%0, %1}, pc;\n\t}"
        : "=f"(r.x), "=f"(r.y) : "f"(a.x), "f"(a.y), "f"(b.x), "f"(b.y));
    return r;
}

__device__ __forceinline__ float2 cmul(float2 a, float2 b) {
    return make_float2(a.x*b.x - a.y*b.y, a.x*b.y + a.y*b.x);
}

// DFT4 (packed): w = -i (fwd) / +i (inv)
template<int INV>
__device__ __forceinline__ void dft4p(float2 b0, float2 b1, float2 b2, float2 b3,
                                      float2& c0, float2& c1, float2& c2, float2& c3)
{
    const float2 apc = padd(b0, b2), amc = psub(b0, b2);
    const float2 bpd = padd(b1, b3), bmd = psub(b1, b3);
    c0 = padd(apc, bpd);
    c2 = psub(apc, bpd);
    const float2 ib = make_float2(-bmd.y, bmd.x);
    if (INV) { c1 = padd(amc, ib); c3 = psub(amc, ib); }
    else     { c1 = psub(amc, ib); c3 = padd(amc, ib); }
}

// DFT8 via even/odd split
template<int INV>
__device__ __forceinline__ void dft8(const float2 a[8], float2 Y[8])
{
    float2 E0,E1,E2,E3, O0,O1,O2,O3;
    dft4p<INV>(a[0],a[2],a[4],a[6], E0,E1,E2,E3);
    dft4p<INV>(a[1],a[3],a[5],a[7], O0,O1,O2,O3);
    const float c = 0.70710678118654752f;
    float2 w1O, w2O, w3O;
    if (INV) {
        w1O = make_float2(c*(O1.x - O1.y),  c*(O1.x + O1.y));
        w2O = make_float2(-O2.y, O2.x);
        w3O = make_float2(-c*(O3.x + O3.y), c*(O3.x - O3.y));
    } else {
        w1O = make_float2(c*(O1.x + O1.y),  c*(O1.y - O1.x));
        w2O = make_float2(O2.y, -O2.x);
        w3O = make_float2(c*(O3.y - O3.x), -c*(O3.x + O3.y));
    }
    Y[0]=padd(E0,O0);  Y[4]=psub(E0,O0);
    Y[1]=padd(E1,w1O); Y[5]=psub(E1,w1O);
    Y[2]=padd(E2,w2O); Y[6]=psub(E2,w2O);
    Y[3]=padd(E3,w3O); Y[7]=psub(E3,w3O);
}

// In-place DIF/DIT radix-8 stage. LSS = log2(span). Group size = 8*span.
// Forward (INV=0): butterfly then twiddle w^{i*m}; Inverse: conj-twiddle then IDFT8.
template<int INV, int LSS>
__device__ __forceinline__ void stage_ip(float2* b, const float2* __restrict__ tw, const int tid)
{
    const int S = 1 << LSS;
    const int i = tid & (S - 1);
    const int e0 = ((tid >> LSS) << (LSS + 3)) + i;
    float2 w1 = tw[i << (10 - LSS)];
    if (INV) w1.y = -w1.y;
    const float2 w2 = cmul(w1, w1);
    const float2 w3 = cmul(w1, w2);
    const float2 w4 = cmul(w2, w2);
    const float2 w5 = cmul(w2, w3);
    const float2 w6 = cmul(w3, w3);
    const float2 w7 = cmul(w3, w4);
    float2 a[8];
    #pragma unroll
    for (int m = 0; m < 8; m++) a[m] = b[PAD(e0 + m * S)];
    if (INV) {
        a[1]=cmul(w1,a[1]); a[2]=cmul(w2,a[2]); a[3]=cmul(w3,a[3]);
        a[4]=cmul(w4,a[4]); a[5]=cmul(w5,a[5]); a[6]=cmul(w6,a[6]); a[7]=cmul(w7,a[7]);
    }
    float2 Y[8];
    dft8<INV>(a, Y);
    if (!INV) {
        Y[1]=cmul(w1,Y[1]); Y[2]=cmul(w2,Y[2]); Y[3]=cmul(w3,Y[3]);
        Y[4]=cmul(w4,Y[4]); Y[5]=cmul(w5,Y[5]); Y[6]=cmul(w6,Y[6]); Y[7]=cmul(w7,Y[7]);
    }
    #pragma unroll
    for (int m = 0; m < 8; m++) b[PAD(e0 + m * S)] = Y[m];
    __syncthreads();
}

// Forward stage 1 (span 1024) fused with gmem load; inputs m=4..7 are zero.
__device__ __forceinline__ void fwd_s1_gmem(const float2* __restrict__ g, float2* b,
                                            const float2* __restrict__ tw, const int tid)
{
    const float2 a0 = g[tid];
    const float2 a1 = g[tid + 1024];
    const float2 a2 = g[tid + 2048];
    const float2 a3 = g[tid + 3072];
    const float2 E0 = padd(a0, a2), E2 = psub(a0, a2);
    const float2 ia2 = make_float2(-a2.y, a2.x);
    const float2 E1 = psub(a0, ia2);
    const float2 E3 = padd(a0, ia2);
    const float2 O0 = padd(a1, a3), O2 = psub(a1, a3);
    const float2 ia3 = make_float2(-a3.y, a3.x);
    const float2 O1 = psub(a1, ia3);
    const float2 O3 = padd(a1, ia3);
    const float c = 0.70710678118654752f;
    const float2 w1O = make_float2(c*(O1.x + O1.y),  c*(O1.y - O1.x));
    const float2 w2O = make_float2(O2.y, -O2.x);
    const float2 w3O = make_float2(c*(O3.y - O3.x), -c*(O3.x + O3.y));
    float2 Y[8];
    Y[0]=padd(E0,O0);  Y[4]=psub(E0,O0);
    Y[1]=padd(E1,w1O); Y[5]=psub(E1,w1O);
    Y[2]=padd(E2,w2O); Y[6]=psub(E2,w2O);
    Y[3]=padd(E3,w3O); Y[7]=psub(E3,w3O);
    const float2 w1 = tw[tid];
    const float2 w2 = cmul(w1, w1);
    const float2 w3 = cmul(w1, w2);
    const float2 w4 = cmul(w2, w2);
    const float2 w5 = cmul(w2, w3);
    const float2 w6 = cmul(w3, w3);
    const float2 w7 = cmul(w3, w4);
    b[PAD(tid         )] = Y[0];
    b[PAD(tid + 1*1024)] = cmul(w1, Y[1]);
    b[PAD(tid + 2*1024)] = cmul(w2, Y[2]);
    b[PAD(tid + 3*1024)] = cmul(w3, Y[3]);
    b[PAD(tid + 4*1024)] = cmul(w4, Y[4]);
    b[PAD(tid + 5*1024)] = cmul(w5, Y[5]);
    b[PAD(tid + 6*1024)] = cmul(w6, Y[6]);
    b[PAD(tid + 7*1024)] = cmul(w7, Y[7]);
    __syncthreads();
}

__device__ __forceinline__ void build_twiddles(float2* tw, int tid)
{
    for (int j = tid; j < 1025; j += TFFT) {
        float s, c;
        sincosf(-6.283185307179586f * (float)j * (1.0f / 8192.0f), &s, &c);
        tw[j] = make_float2(c, s);
    }
    __syncthreads();
}

// rfft unpack: S[j] = E + T, S[N-j] = conj(E - T); W16 = e^{-i pi j/N}
__device__ __forceinline__ void rfft_pair(float2 Cj, float2 Cn, float2 W16,
                                          float2& Sj, float2& Snj)
{
    const float2 E = make_float2(0.5f*(Cj.x + Cn.x), 0.5f*(Cj.y - Cn.y));
    const float2 O = make_float2(0.5f*(Cj.y + Cn.y), -0.5f*(Cj.x - Cn.x));
    const float2 T = cmul(W16, O);
    Sj  = padd(E, T);
    const float2 emt = psub(E, T);
    Snj = make_float2(emt.x, -emt.y);
}

// repack: G[j], G[nj] from Pj = S[j]*K[j], Pn = S[nj]*K[nj]
__device__ __forceinline__ void repack(float2 Pj, float2 Pn, float2 W16,
                                       float2& Gj, float2& Gn)
{
    {
        const float2 U  = make_float2(Pj.x + Pn.x, Pj.y - Pn.y);
        const float2 Wd = make_float2(Pj.x - Pn.x, Pj.y + Pn.y);
        const float2 V  = make_float2(W16.x, -W16.y);
        const float2 VW = cmul(V, Wd);
        Gj = make_float2(U.x - VW.y, U.y + VW.x);
    }
    {
        const float2 U  = make_float2(Pn.x + Pj.x, Pn.y - Pj.y);
        const float2 Wd = make_float2(Pn.x - Pj.x, Pn.y + Pj.y);
        const float2 V  = make_float2(-W16.x, -W16.y);
        const float2 VW = cmul(V, Wd);
        Gn = make_float2(U.x - VW.y, U.y + VW.x);
    }
}

// digit-scrambled position of frequency j (<4096): pair (p, p+1) holds (j, j+4096)
__device__ __forceinline__ int pmap(int j) {
    return ((j & 7) << 10) + (((j >> 3) & 7) << 7) + (((j >> 6) & 7) << 4) + (((j >> 9) & 7) << 1);
}

// e^{-i pi/8192}
#define W0X 0.99999992646571789f
#define W0Y (-3.8349518757139556e-4f)

// ---------------- kernel A1: MLP layers 1-3 ----------------
__global__ void k_mlp(const float* __restrict__ z, const float* __restrict__ freq,
                      const float* __restrict__ W1, const float* __restrict__ b1,
                      const float* __restrict__ W2, const float* __restrict__ b2,
                      const float* __restrict__ W3, const float* __restrict__ b3)
{
    __shared__ float zs [4][33];
    __shared__ float hs [4][64];
    __shared__ float hs2[4][64];
    const int f = threadIdx.x & 63;
    const int g = threadIdx.x >> 6;
    const int l = blockIdx.x * 4 + g;

    if (f < 33) zs[g][f] = z[l * 33 + f];
    __syncthreads();

    const float fr = freq[f];
    float acc = b1[f];
    #pragma unroll
    for (int e = 0; e < 33; e++) acc = fmaf(zs[g][e], W1[e * 64 + f], acc);
    hs[g][f] = sinf(fr * acc);
    __syncthreads();

    acc = b2[f];
    #pragma unroll
    for (int e = 0; e < 64; e++) acc = fmaf(hs[g][e], W2[e * 64 + f], acc);
    hs2[g][f] = sinf(fr * acc);
    __syncthreads();

    acc = b3[f];
    #pragma unroll
    for (int e = 0; e < 64; e++) acc = fmaf(hs2[g][e], W3[e * 64 + f], acc);
    g_h3[l * 64 + f] = sinf(fr * acc);
}

// ---------------- kernel A2: k = (h3 @ Wout) * window, transposed to d-major ----
__global__ void k_wout(const float* __restrict__ Wout, const float* __restrict__ t,
                       const float* __restrict__ deltas)
{
    __shared__ float h3s[16 * 64];
    __shared__ float ts[16];
    const int tid = threadIdx.x;
    const int l0 = blockIdx.x * 16;

    for (int i = tid; i < 1024; i += 256) h3s[i] = g_h3[l0 * 64 + i];
    if (tid < 16) ts[tid] = t[l0 + tid];
    __syncthreads();

    float acc[3][16];
    #pragma unroll
    for (int j = 0; j < 3; j++)
        #pragma unroll
        for (int l = 0; l < 16; l++) acc[j][l] = 0.0f;

    #pragma unroll 4
    for (int f = 0; f < 64; f++) {
        const float w0 = Wout[f * 768 + tid];
        const float w1 = Wout[f * 768 + tid + 256];
        const float w2 = Wout[f * 768 + tid + 512];
        #pragma unroll
        for (int l = 0; l < 16; l++) {
            const float h = h3s[l * 64 + f];
            acc[0][l] = fmaf(h, w0, acc[0][l]);
            acc[1][l] = fmaf(h, w1, acc[1][l]);
            acc[2][l] = fmaf(h, w2, acc[2][l]);
        }
    }

    #pragma unroll
    for (int j = 0; j < 3; j++) {
        const int d = tid + j * 256;
        const float ad = fabsf(deltas[d]);
        float v[16];
        #pragma unroll
        for (int l = 0; l < 16; l++)
            v[l] = acc[j][l] * (expf(-ts[l] * ad) + 0.05f);
        float4* dst = (float4*)(g_k + (size_t)d * LSEQ + l0);
        dst[0] = make_float4(v[0],  v[1],  v[2],  v[3]);
        dst[1] = make_float4(v[4],  v[5],  v[6],  v[7]);
        dst[2] = make_float4(v[8],  v[9],  v[10], v[11]);
        dst[3] = make_float4(v[12], v[13], v[14], v[15]);
    }
}

// ---------------- kernel B: Kf[d][j] = rfft(k_d, 16384)[j] / 16384 ----------------
__global__ void __launch_bounds__(TFFT, 2) k_kfft()
{
    extern __shared__ float2 smem[];
    float2* b  = smem;
    float2* tw = smem + BUFSZ;
    const int tid = threadIdx.x;
    const int d = blockIdx.x;

    build_twiddles(tw, tid);
    const float2* kr = (const float2*)(g_k + (size_t)d * LSEQ);

    fwd_s1_gmem(kr, b, tw, tid);
    stage_ip<0, 7>(b, tw, tid);
    stage_ip<0, 4>(b, tw, tid);
    stage_ip<0, 1>(b, tw, tid);
    // scrambled radix-8 partials in b; final radix-2 fused into the unpack below

    float2* Kf = g_Kf + (size_t)d * 8200;
    const float sc = 1.0f / 16384.0f;

    if (tid == 0) {
        const float2 u = b[PAD(0)], v = b[PAD(1)];
        const float2 C0 = padd(u, v);
        const float2 Cm = psub(u, v);          // C[4096]
        Kf[0]    = make_float2((C0.x + C0.y) * sc, 0.f);
        Kf[8192] = make_float2((C0.x - C0.y) * sc, 0.f);
        Kf[4096] = make_float2(Cm.x * sc, -Cm.y * sc);
    }
    #pragma unroll
    for (int it = 0; it < 2; it++) {
        const int j  = tid + 1 + it * 1024;     // 1..2048
        const int jp = 4096 - j;
        const int nj = 8192 - j;
        const int njp = 4096 + j;
        const int P1 = pmap(j);
        const int P2 = pmap(jp);
        const float2 u1 = b[PAD(P1)], v1 = b[PAD(P1 + 1)];
        const float2 u2 = b[PAD(P2)], v2 = b[PAD(P2 + 1)];
        const float2 Cj   = padd(u1, v1);
        const float2 Cnjp = psub(u1, v1);
        const float2 Cjp  = padd(u2, v2);
        const float2 Cnj  = psub(u2, v2);
        float2 W16 = tw[j >> 1];
        if (j & 1) W16 = cmul(W16, make_float2(W0X, W0Y));
        const float2 W16p = make_float2(-W16.y, -W16.x);   // W16(4096-j)
        float2 Sj, Snj, Sjp, Snjp;
        rfft_pair(Cj,  Cnj,  W16,  Sj,  Snj);
        rfft_pair(Cjp, Cnjp, W16p, Sjp, Snjp);
        Kf[j]   = make_float2(Sj.x * sc,   Sj.y * sc);
        Kf[nj]  = make_float2(Snj.x * sc,  Snj.y * sc);
        Kf[jp]  = make_float2(Sjp.x * sc,  Sjp.y * sc);
        Kf[njp] = make_float2(Snjp.x * sc, Snjp.y * sc);
    }
}

// ---------------- kernel C: per-row fused rFFT -> multiply -> irFFT -> +D*x --------
__global__ void __launch_bounds__(TFFT, 2) k_conv(const float* __restrict__ x,
                                                  const float* __restrict__ Dv,
                                                  float* __restrict__ out)
{
    extern __shared__ float2 smem[];
    float2* b  = smem;
    float2* tw = smem + BUFSZ;
    const int tid = threadIdx.x;
    const int row = blockIdx.x;
    const int d = row % DM;

    build_twiddles(tw, tid);
    const float2* x2 = (const float2*)(x + (size_t)row * LSEQ);

    // forward: in-place DIF, spans 1024/128/16/2 (final radix-2 fused below)
    fwd_s1_gmem(x2, b, tw, tid);
    stage_ip<0, 7>(b, tw, tid);
    stage_ip<0, 4>(b, tw, tid);
    stage_ip<0, 1>(b, tw, tid);

    // spectral (in-place): fold fwd radix-2, unpack, *Kf, repack, fold inv radix-2
    const float2* __restrict__ Kf = g_Kf + (size_t)d * 8200;

    if (tid == 0) {
        const float2 u = b[PAD(0)], v = b[PAD(1)];
        const float2 C0 = padd(u, v);
        const float2 Cm = psub(u, v);                       // C[4096]
        const float S0 = C0.x + C0.y;
        const float SN = C0.x - C0.y;
        const float2 K0 = Kf[0];
        const float2 KN = Kf[8192];
        const float2 P0 = make_float2(S0 * K0.x, S0 * K0.y);
        const float2 PN = make_float2(SN * KN.x, SN * KN.y);
        const float2 U = padd(P0, PN);
        const float2 W = psub(P0, PN);
        const float2 G0 = make_float2(U.x - W.y, U.y + W.x);
        const float2 Sm = make_float2(Cm.x, -Cm.y);
        const float2 Pm = cmul(Sm, Kf[4096]);
        const float2 G4096 = make_float2(2.0f * Pm.x, -2.0f * Pm.y);
        b[PAD(0)] = padd(G0, G4096);
        b[PAD(1)] = psub(G0, G4096);
    }
    #pragma unroll
    for (int it = 0; it < 2; it++) {
        const int j  = tid + 1 + it * 1024;     // 1..2048 (j=2048 self-paired, idempotent)
        const int jp = 4096 - j;
        const int nj = 8192 - j;
        const int njp = 4096 + j;
        const int P1 = pmap(j);
        const int P2 = pmap(jp);
        const int a1i = PAD(P1), b1i = PAD(P1 + 1);
        const int a2i = PAD(P2), b2i = PAD(P2 + 1);
        const float2 u1 = b[a1i], v1 = b[b1i];
        const float2 u2 = b[a2i], v2 = b[b2i];
        const float2 Cj   = padd(u1, v1);   // C[j]
        const float2 Cnjp = psub(u1, v1);   // C[j+4096]
        const float2 Cjp  = padd(u2, v2);   // C[4096-j]
        const float2 Cnj  = psub(u2, v2);   // C[8192-j]
        float2 W16 = tw[j >> 1];
        if (j & 1) W16 = cmul(W16, make_float2(W0X, W0Y));
        const float2 W16p = make_float2(-W16.y, -W16.x);
        float2 Sj, Snj, Sjp, Snjp;
        rfft_pair(Cj,  Cnj,  W16,  Sj,  Snj);
        rfft_pair(Cjp, Cnjp, W16p, Sjp, Snjp);
        const float2 Pj   = cmul(Sj,   Kf[j]);
        const float2 Pnj  = cmul(Snj,  Kf[nj]);
        const float2 Pjp  = cmul(Sjp,  Kf[jp]);
        const float2 Pnjp = cmul(Snjp, Kf[njp]);
        float2 Gj, Gnj, Gjp, Gnjp;
        repack(Pj,  Pnj,  W16,  Gj,  Gnj);
        repack(Pjp, Pnjp, W16p, Gjp, Gnjp);
        // inverse radix-2 fold: pair (P1,P1+1) holds freqs (j, j+4096); (P2,P2+1): (4096-j, 8192-j)
        b[a1i] = padd(Gj,  Gnjp);
        b[b1i] = psub(Gj,  Gnjp);
        b[a2i] = padd(Gjp, Gnj);
        b[b2i] = psub(Gjp, Gnj);
    }
    __syncthreads();

    // inverse: in-place DIT, spans 2/16/128, last span-1024 stage fused with epilogue
    stage_ip<1, 1>(b, tw, tid);
    stage_ip<1, 4>(b, tw, tid);
    stage_ip<1, 7>(b, tw, tid);

    // S1^-1 (span 1024) + epilogue: need only outputs m=0..3 (n < 4096)
    {
        float2 w1 = tw[tid]; w1.y = -w1.y;
        const float2 w2 = cmul(w1, w1);
        const float2 w3 = cmul(w1, w2);
        const float2 w4 = cmul(w2, w2);
        const float2 w5 = cmul(w2, w3);
        const float2 w6 = cmul(w3, w3);
        const float2 w7 = cmul(w3, w4);
        float2 a[8];
        a[0] = b[PAD(tid)];
        a[1] = cmul(w1, b[PAD(tid + 1*1024)]);
        a[2] = cmul(w2, b[PAD(tid + 2*1024)]);
        a[3] = cmul(w3, b[PAD(tid + 3*1024)]);
        a[4] = cmul(w4, b[PAD(tid + 4*1024)]);
        a[5] = cmul(w5, b[PAD(tid + 5*1024)]);
        a[6] = cmul(w6, b[PAD(tid + 6*1024)]);
        a[7] = cmul(w7, b[PAD(tid + 7*1024)]);
        float2 E0,E1,E2,E3, O0,O1,O2,O3;
        dft4p<1>(a[0],a[2],a[4],a[6], E0,E1,E2,E3);
        dft4p<1>(a[1],a[3],a[5],a[7], O0,O1,O2,O3);
        const float c = 0.70710678118654752f;
        const float2 w1O = make_float2(c*(O1.x - O1.y),  c*(O1.x + O1.y));
        const float2 w2O = make_float2(-O2.y, O2.x);
        const float2 w3O = make_float2(-c*(O3.x + O3.y), c*(O3.x - O3.y));
        float2 z0 = padd(E0, O0);
        float2 z1 = padd(E1, w1O);
        float2 z2 = padd(E2, w2O);
        float2 z3 = padd(E3, w3O);
        const float Dd = Dv[d];
        float2* o2 = (float2*)(out + (size_t)row * LSEQ);
        const float2 xv0 = x2[tid];
        const float2 xv1 = x2[tid + 1024];
        const float2 xv2 = x2[tid + 2048];
        const float2 xv3 = x2[tid + 3072];
        o2[tid       ] = make_float2(fmaf(Dd, xv0.x, z0.x), fmaf(Dd, xv0.y, z0.y));
        o2[tid + 1024] = make_float2(fmaf(Dd, xv1.x, z1.x), fmaf(Dd, xv1.y, z1.y));
        o2[tid + 2048] = make_float2(fmaf(Dd, xv2.x, z2.x), fmaf(Dd, xv2.y, z2.y));
        o2[tid + 3072] = make_float2(fmaf(Dd, xv3.x, z3.x), fmaf(Dd, xv3.y, z3.y));
    }
}

// ---------------- launch ----------------
extern "C" void kernel_launch(void* const* d_in, const int* in_sizes, int n_in,
                              void* d_out, int out_size)
{
    const float* x      = (const float*)d_in[0];
    const float* z      = (const float*)d_in[1];
    const float* t      = (const float*)d_in[2];
    const float* freq   = (const float*)d_in[3];
    const float* W1     = (const float*)d_in[4];
    const float* b1     = (const float*)d_in[5];
    const float* W2     = (const float*)d_in[6];
    const float* b2     = (const float*)d_in[7];
    const float* W3     = (const float*)d_in[8];
    const float* b3     = (const float*)d_in[9];
    const float* Wout   = (const float*)d_in[10];
    const float* deltas = (const float*)d_in[11];
    const float* Dv     = (const float*)d_in[12];
    float* out = (float*)d_out;

    cudaFuncSetAttribute(k_kfft, cudaFuncAttributeMaxDynamicSharedMemorySize, SMEM_BYTES);
    cudaFuncSetAttribute(k_conv, cudaFuncAttributeMaxDynamicSharedMemorySize, SMEM_BYTES);

    k_mlp <<<LSEQ / 4, 256>>>(z, freq, W1, b1, W2, b2, W3, b3);
    k_wout<<<LSEQ / 16, 256>>>(Wout, t, deltas);
    k_kfft<<<DM, TFFT, SMEM_BYTES>>>();
    k_conv<<<BATCH * DM, TFFT, SMEM_BYTES>>>(x, Dv, out);
}

// round 9
// speedup vs baseline: 2.2173x; 1.1410x over previous
#include <cuda_runtime.h>
#include <math.h>
#include <stdint.h>

#define NFFT 8192
#define LSEQ 8192
#define DM   768
#define BATCH 4
#define TFFT 1024
// In-place buffer pad: breaks stride-1024/128/16 conflicts; all FFT data stages conflict-free.
#define PAD(a) ((a) + ((a) >> 4) + ((a) >> 9))
#define BUFSZ 8720   // PAD(8191)=8717
// Twiddle table pad: makes strided tw reads (idx = 8t, 64t) conflict-free.
#define TWP(j) ((j) + ((j) >> 3) + ((j) >> 6))
#define TWSZ  1170   // TWP(1024)=1168
#define SMEM_BYTES ((BUFSZ + TWSZ) * (int)sizeof(float2))  // 79120

// ---------------- scratch (device globals; no runtime allocation) ----------------
__device__ __align__(16) float  g_h3[LSEQ * 64];
__device__ __align__(16) float  g_k [DM * LSEQ];
__device__ __align__(16) float2 g_Kf[DM * 8200];   // half-spectra 0..8192, stride 8200

// ---------------- packed f32x2 helpers ----------------
__device__ __forceinline__ float2 padd(float2 a, float2 b) {
    float2 r;
    asm("{\n\t.reg .b64 pa, pb, pc;\n\t"
        "mov.b64 pa, {%2, %3};\n\tmov.b64 pb, {%4, %5};\n\t"
        "add.rn.f32x2 pc, pa, pb;\n\tmov.b64 {%0, %1}, pc;\n\t}"
        : "=f"(r.x), "=f"(r.y) : "f"(a.x), "f"(a.y), "f"(b.x), "f"(b.y));
    return r;
}
__device__ __forceinline__ float2 psub(float2 a, float2 b) {
    float2 r;
    asm("{\n\t.reg .b64 pa, pb, pc;\n\t"
        "mov.b64 pa, {%2, %3};\n\tmov.b64 pb, {%4, %5};\n\t"
        "sub.rn.f32x2 pc, pa, pb;\n\tmov.b64 {%0, %1}, pc;\n\t}"
        : "=f"(r.x), "=f"(r.y) : "f"(a.x), "f"(a.y), "f"(b.x), "f"(b.y));
    return r;
}

__device__ __forceinline__ float2 cmul(float2 a, float2 b) {
    return make_float2(a.x*b.x - a.y*b.y, a.x*b.y + a.y*b.x);
}

// DFT4 (packed): w = -i (fwd) / +i (inv)
template<int INV>
__device__ __forceinline__ void dft4p(float2 b0, float2 b1, float2 b2, float2 b3,
                                      float2& c0, float2& c1, float2& c2, float2& c3)
{
    const float2 apc = padd(b0, b2), amc = psub(b0, b2);
    const float2 bpd = padd(b1, b3), bmd = psub(b1, b3);
    c0 = padd(apc, bpd);
    c2 = psub(apc, bpd);
    const float2 ib = make_float2(-bmd.y, bmd.x);
    if (INV) { c1 = padd(amc, ib); c3 = psub(amc, ib); }
    else     { c1 = psub(amc, ib); c3 = padd(amc, ib); }
}

// DFT8 via even/odd split
template<int INV>
__device__ __forceinline__ void dft8(const float2 a[8], float2 Y[8])
{
    float2 E0,E1,E2,E3, O0,O1,O2,O3;
    dft4p<INV>(a[0],a[2],a[4],a[6], E0,E1,E2,E3);
    dft4p<INV>(a[1],a[3],a[5],a[7], O0,O1,O2,O3);
    const float c = 0.70710678118654752f;
    float2 w1O, w2O, w3O;
    if (INV) {
        w1O = make_float2(c*(O1.x - O1.y),  c*(O1.x + O1.y));
        w2O = make_float2(-O2.y, O2.x);
        w3O = make_float2(-c*(O3.x + O3.y), c*(O3.x - O3.y));
    } else {
        w1O = make_float2(c*(O1.x + O1.y),  c*(O1.y - O1.x));
        w2O = make_float2(O2.y, -O2.x);
        w3O = make_float2(c*(O3.y - O3.x), -c*(O3.x + O3.y));
    }
    Y[0]=padd(E0,O0);  Y[4]=psub(E0,O0);
    Y[1]=padd(E1,w1O); Y[5]=psub(E1,w1O);
    Y[2]=padd(E2,w2O); Y[6]=psub(E2,w2O);
    Y[3]=padd(E3,w3O); Y[7]=psub(E3,w3O);
}

// In-place DIF/DIT radix-8 stage. LSS = log2(span).
// LSS==1 uses a remapped thread->butterfly assignment (conflict-free data banks;
// twiddle becomes a phase-broadcast). Other LSS keep the natural mapping (clean).
template<int INV, int LSS>
__device__ __forceinline__ void stage_ip(float2* b, const float2* __restrict__ tw, const int tid)
{
    const int S = 1 << LSS;
    int i, e0;
    if (LSS == 1) {
        i  = tid >> 9;                 // 0..1
        const int grp = tid & 511;
        e0 = (grp << 4) + i;
    } else {
        i  = tid & (S - 1);
        e0 = ((tid >> LSS) << (LSS + 3)) + i;
    }
    float2 w1 = tw[TWP(i << (10 - LSS))];
    if (INV) w1.y = -w1.y;
    const float2 w2 = cmul(w1, w1);
    const float2 w3 = cmul(w1, w2);
    const float2 w4 = cmul(w2, w2);
    const float2 w5 = cmul(w2, w3);
    const float2 w6 = cmul(w3, w3);
    const float2 w7 = cmul(w3, w4);
    float2 a[8];
    #pragma unroll
    for (int m = 0; m < 8; m++) a[m] = b[PAD(e0 + m * S)];
    if (INV) {
        a[1]=cmul(w1,a[1]); a[2]=cmul(w2,a[2]); a[3]=cmul(w3,a[3]);
        a[4]=cmul(w4,a[4]); a[5]=cmul(w5,a[5]); a[6]=cmul(w6,a[6]); a[7]=cmul(w7,a[7]);
    }
    float2 Y[8];
    dft8<INV>(a, Y);
    if (!INV) {
        Y[1]=cmul(w1,Y[1]); Y[2]=cmul(w2,Y[2]); Y[3]=cmul(w3,Y[3]);
        Y[4]=cmul(w4,Y[4]); Y[5]=cmul(w5,Y[5]); Y[6]=cmul(w6,Y[6]); Y[7]=cmul(w7,Y[7]);
    }
    #pragma unroll
    for (int m = 0; m < 8; m++) b[PAD(e0 + m * S)] = Y[m];
    __syncthreads();
}

// Forward stage 1 (span 1024) fused with gmem load; inputs m=4..7 are zero.
__device__ __forceinline__ void fwd_s1_gmem(const float2* __restrict__ g, float2* b,
                                            const float2* __restrict__ tw, const int tid)
{
    const float2 a0 = g[tid];
    const float2 a1 = g[tid + 1024];
    const float2 a2 = g[tid + 2048];
    const float2 a3 = g[tid + 3072];
    const float2 E0 = padd(a0, a2), E2 = psub(a0, a2);
    const float2 ia2 = make_float2(-a2.y, a2.x);
    const float2 E1 = psub(a0, ia2);
    const float2 E3 = padd(a0, ia2);
    const float2 O0 = padd(a1, a3), O2 = psub(a1, a3);
    const float2 ia3 = make_float2(-a3.y, a3.x);
    const float2 O1 = psub(a1, ia3);
    const float2 O3 = padd(a1, ia3);
    const float c = 0.70710678118654752f;
    const float2 w1O = make_float2(c*(O1.x + O1.y),  c*(O1.y - O1.x));
    const float2 w2O = make_float2(O2.y, -O2.x);
    const float2 w3O = make_float2(c*(O3.y - O3.x), -c*(O3.x + O3.y));
    float2 Y[8];
    Y[0]=padd(E0,O0);  Y[4]=psub(E0,O0);
    Y[1]=padd(E1,w1O); Y[5]=psub(E1,w1O);
    Y[2]=padd(E2,w2O); Y[6]=psub(E2,w2O);
    Y[3]=padd(E3,w3O); Y[7]=psub(E3,w3O);
    const float2 w1 = tw[TWP(tid)];
    const float2 w2 = cmul(w1, w1);
    const float2 w3 = cmul(w1, w2);
    const float2 w4 = cmul(w2, w2);
    const float2 w5 = cmul(w2, w3);
    const float2 w6 = cmul(w3, w3);
    const float2 w7 = cmul(w3, w4);
    b[PAD(tid         )] = Y[0];
    b[PAD(tid + 1*1024)] = cmul(w1, Y[1]);
    b[PAD(tid + 2*1024)] = cmul(w2, Y[2]);
    b[PAD(tid + 3*1024)] = cmul(w3, Y[3]);
    b[PAD(tid + 4*1024)] = cmul(w4, Y[4]);
    b[PAD(tid + 5*1024)] = cmul(w5, Y[5]);
    b[PAD(tid + 6*1024)] = cmul(w6, Y[6]);
    b[PAD(tid + 7*1024)] = cmul(w7, Y[7]);
    __syncthreads();
}

__device__ __forceinline__ void build_twiddles(float2* tw, int tid)
{
    for (int j = tid; j < 1025; j += TFFT) {
        float s, c;
        sincosf(-6.283185307179586f * (float)j * (1.0f / 8192.0f), &s, &c);
        tw[TWP(j)] = make_float2(c, s);
    }
    __syncthreads();
}

// rfft unpack: S[j] = E + T, S[N-j] = conj(E - T); W16 = e^{-i pi j/N}
__device__ __forceinline__ void rfft_pair(float2 Cj, float2 Cn, float2 W16,
                                          float2& Sj, float2& Snj)
{
    const float2 E = make_float2(0.5f*(Cj.x + Cn.x), 0.5f*(Cj.y - Cn.y));
    const float2 O = make_float2(0.5f*(Cj.y + Cn.y), -0.5f*(Cj.x - Cn.x));
    const float2 T = cmul(W16, O);
    Sj  = padd(E, T);
    const float2 emt = psub(E, T);
    Snj = make_float2(emt.x, -emt.y);
}

// repack: G[j], G[nj] from Pj = S[j]*K[j], Pn = S[nj]*K[nj]
__device__ __forceinline__ void repack(float2 Pj, float2 Pn, float2 W16,
                                       float2& Gj, float2& Gn)
{
    {
        const float2 U  = make_float2(Pj.x + Pn.x, Pj.y - Pn.y);
        const float2 Wd = make_float2(Pj.x - Pn.x, Pj.y + Pn.y);
        const float2 V  = make_float2(W16.x, -W16.y);
        const float2 VW = cmul(V, Wd);
        Gj = make_float2(U.x - VW.y, U.y + VW.x);
    }
    {
        const float2 U  = make_float2(Pn.x + Pj.x, Pn.y - Pj.y);
        const float2 Wd = make_float2(Pn.x - Pj.x, Pn.y + Pj.y);
        const float2 V  = make_float2(-W16.x, -W16.y);
        const float2 VW = cmul(V, Wd);
        Gn = make_float2(U.x - VW.y, U.y + VW.x);
    }
}

// digit-scrambled position of frequency j (<4096): pair (p, p+1) holds (j, j+4096)
__device__ __forceinline__ int pmap(int j) {
    return ((j & 7) << 10) + (((j >> 3) & 7) << 7) + (((j >> 6) & 7) << 4) + (((j >> 9) & 7) << 1);
}

// e^{-i pi/8192}
#define W0X 0.99999992646571789f
#define W0Y (-3.8349518757139556e-4f)

// ---------------- kernel A1: MLP layers 1-3 ----------------
__global__ void k_mlp(const float* __restrict__ z, const float* __restrict__ freq,
                      const float* __restrict__ W1, const float* __restrict__ b1,
                      const float* __restrict__ W2, const float* __restrict__ b2,
                      const float* __restrict__ W3, const float* __restrict__ b3)
{
    __shared__ float zs [4][33];
    __shared__ float hs [4][64];
    __shared__ float hs2[4][64];
    const int f = threadIdx.x & 63;
    const int g = threadIdx.x >> 6;
    const int l = blockIdx.x * 4 + g;

    if (f < 33) zs[g][f] = z[l * 33 + f];
    __syncthreads();

    const float fr = freq[f];
    float acc = b1[f];
    #pragma unroll
    for (int e = 0; e < 33; e++) acc = fmaf(zs[g][e], W1[e * 64 + f], acc);
    hs[g][f] = sinf(fr * acc);
    __syncthreads();

    acc = b2[f];
    #pragma unroll
    for (int e = 0; e < 64; e++) acc = fmaf(hs[g][e], W2[e * 64 + f], acc);
    hs2[g][f] = sinf(fr * acc);
    __syncthreads();

    acc = b3[f];
    #pragma unroll
    for (int e = 0; e < 64; e++) acc = fmaf(hs2[g][e], W3[e * 64 + f], acc);
    g_h3[l * 64 + f] = sinf(fr * acc);
}

// ---------------- kernel A2: k = (h3 @ Wout) * window, transposed to d-major ----
__global__ void k_wout(const float* __restrict__ Wout, const float* __restrict__ t,
                       const float* __restrict__ deltas)
{
    __shared__ float h3s[16 * 64];
    __shared__ float ts[16];
    const int tid = threadIdx.x;
    const int l0 = blockIdx.x * 16;

    for (int i = tid; i < 1024; i += 256) h3s[i] = g_h3[l0 * 64 + i];
    if (tid < 16) ts[tid] = t[l0 + tid];
    __syncthreads();

    float acc[3][16];
    #pragma unroll
    for (int j = 0; j < 3; j++)
        #pragma unroll
        for (int l = 0; l < 16; l++) acc[j][l] = 0.0f;

    #pragma unroll 4
    for (int f = 0; f < 64; f++) {
        const float w0 = Wout[f * 768 + tid];
        const float w1 = Wout[f * 768 + tid + 256];
        const float w2 = Wout[f * 768 + tid + 512];
        #pragma unroll
        for (int l = 0; l < 16; l++) {
            const float h = h3s[l * 64 + f];
            acc[0][l] = fmaf(h, w0, acc[0][l]);
            acc[1][l] = fmaf(h, w1, acc[1][l]);
            acc[2][l] = fmaf(h, w2, acc[2][l]);
        }
    }

    #pragma unroll
    for (int j = 0; j < 3; j++) {
        const int d = tid + j * 256;
        const float ad = fabsf(deltas[d]);
        float v[16];
        #pragma unroll
        for (int l = 0; l < 16; l++)
            v[l] = acc[j][l] * (expf(-ts[l] * ad) + 0.05f);
        float4* dst = (float4*)(g_k + (size_t)d * LSEQ + l0);
        dst[0] = make_float4(v[0],  v[1],  v[2],  v[3]);
        dst[1] = make_float4(v[4],  v[5],  v[6],  v[7]);
        dst[2] = make_float4(v[8],  v[9],  v[10], v[11]);
        dst[3] = make_float4(v[12], v[13], v[14], v[15]);
    }
}

// ---------------- kernel B: Kf[d][j] = rfft(k_d, 16384)[j] / 16384 ----------------
__global__ void __launch_bounds__(TFFT, 2) k_kfft()
{
    extern __shared__ float2 smem[];
    float2* b  = smem;
    float2* tw = smem + BUFSZ;
    const int tid = threadIdx.x;
    const int d = blockIdx.x;

    build_twiddles(tw, tid);
    const float2* kr = (const float2*)(g_k + (size_t)d * LSEQ);

    fwd_s1_gmem(kr, b, tw, tid);
    stage_ip<0, 7>(b, tw, tid);
    stage_ip<0, 4>(b, tw, tid);
    stage_ip<0, 1>(b, tw, tid);
    // scrambled radix-8 partials in b; final radix-2 fused into the unpack below

    float2* Kf = g_Kf + (size_t)d * 8200;
    const float sc = 1.0f / 16384.0f;

    if (tid == 0) {
        const float2 u = b[PAD(0)], v = b[PAD(1)];
        const float2 C0 = padd(u, v);
        const float2 Cm = psub(u, v);          // C[4096]
        Kf[0]    = make_float2((C0.x + C0.y) * sc, 0.f);
        Kf[8192] = make_float2((C0.x - C0.y) * sc, 0.f);
        Kf[4096] = make_float2(Cm.x * sc, -Cm.y * sc);
    }
    #pragma unroll
    for (int it = 0; it < 2; it++) {
        const int j  = tid + 1 + it * 1024;     // 1..2048
        const int jp = 4096 - j;
        const int nj = 8192 - j;
        const int njp = 4096 + j;
        const int P1 = pmap(j);
        const int P2 = pmap(jp);
        const float2 u1 = b[PAD(P1)], v1 = b[PAD(P1 + 1)];
        const float2 u2 = b[PAD(P2)], v2 = b[PAD(P2 + 1)];
        const float2 Cj   = padd(u1, v1);
        const float2 Cnjp = psub(u1, v1);
        const float2 Cjp  = padd(u2, v2);
        const float2 Cnj  = psub(u2, v2);
        float2 W16 = tw[TWP(j >> 1)];
        if (j & 1) W16 = cmul(W16, make_float2(W0X, W0Y));
        const float2 W16p = make_float2(-W16.y, -W16.x);   // W16(4096-j)
        float2 Sj, Snj, Sjp, Snjp;
        rfft_pair(Cj,  Cnj,  W16,  Sj,  Snj);
        rfft_pair(Cjp, Cnjp, W16p, Sjp, Snjp);
        Kf[j]   = make_float2(Sj.x * sc,   Sj.y * sc);
        Kf[nj]  = make_float2(Snj.x * sc,  Snj.y * sc);
        Kf[jp]  = make_float2(Sjp.x * sc,  Sjp.y * sc);
        Kf[njp] = make_float2(Snjp.x * sc, Snjp.y * sc);
    }
}

// ---------------- kernel C: per-row fused rFFT -> multiply -> irFFT -> +D*x --------
__global__ void __launch_bounds__(TFFT, 2) k_conv(const float* __restrict__ x,
                                                  const float* __restrict__ Dv,
                                                  float* __restrict__ out)
{
    extern __shared__ float2 smem[];
    float2* b  = smem;
    float2* tw = smem + BUFSZ;
    const int tid = threadIdx.x;
    const int row = blockIdx.x;
    const int d = row % DM;

    build_twiddles(tw, tid);
    const float2* x2 = (const float2*)(x + (size_t)row * LSEQ);

    // forward: in-place DIF, spans 1024/128/16/2 (final radix-2 fused below)
    fwd_s1_gmem(x2, b, tw, tid);
    stage_ip<0, 7>(b, tw, tid);
    stage_ip<0, 4>(b, tw, tid);
    stage_ip<0, 1>(b, tw, tid);

    // spectral (in-place): fold fwd radix-2, unpack, *Kf, repack, fold inv radix-2
    const float2* __restrict__ Kf = g_Kf + (size_t)d * 8200;

    if (tid == 0) {
        const float2 u = b[PAD(0)], v = b[PAD(1)];
        const float2 C0 = padd(u, v);
        const float2 Cm = psub(u, v);                       // C[4096]
        const float S0 = C0.x + C0.y;
        const float SN = C0.x - C0.y;
        const float2 K0 = Kf[0];
        const float2 KN = Kf[8192];
        const float2 P0 = make_float2(S0 * K0.x, S0 * K0.y);
        const float2 PN = make_float2(SN * KN.x, SN * KN.y);
        const float2 U = padd(P0, PN);
        const float2 W = psub(P0, PN);
        const float2 G0 = make_float2(U.x - W.y, U.y + W.x);
        const float2 Sm = make_float2(Cm.x, -Cm.y);
        const float2 Pm = cmul(Sm, Kf[4096]);
        const float2 G4096 = make_float2(2.0f * Pm.x, -2.0f * Pm.y);
        b[PAD(0)] = padd(G0, G4096);
        b[PAD(1)] = psub(G0, G4096);
    }
    #pragma unroll
    for (int it = 0; it < 2; it++) {
        const int j  = tid + 1 + it * 1024;     // 1..2048 (j=2048 self-paired, idempotent)
        const int jp = 4096 - j;
        const int nj = 8192 - j;
        const int njp = 4096 + j;
        const int P1 = pmap(j);
        const int P2 = pmap(jp);
        const int a1i = PAD(P1), b1i = PAD(P1 + 1);
        const int a2i = PAD(P2), b2i = PAD(P2 + 1);
        const float2 u1 = b[a1i], v1 = b[b1i];
        const float2 u2 = b[a2i], v2 = b[b2i];
        const float2 Cj   = padd(u1, v1);   // C[j]
        const float2 Cnjp = psub(u1, v1);   // C[j+4096]
        const float2 Cjp  = padd(u2, v2);   // C[4096-j]
        const float2 Cnj  = psub(u2, v2);   // C[8192-j]
        float2 W16 = tw[TWP(j >> 1)];
        if (j & 1) W16 = cmul(W16, make_float2(W0X, W0Y));
        const float2 W16p = make_float2(-W16.y, -W16.x);
        float2 Sj, Snj, Sjp, Snjp;
        rfft_pair(Cj,  Cnj,  W16,  Sj,  Snj);
        rfft_pair(Cjp, Cnjp, W16p, Sjp, Snjp);
        const float2 Pj   = cmul(Sj,   Kf[j]);
        const float2 Pnj  = cmul(Snj,  Kf[nj]);
        const float2 Pjp  = cmul(Sjp,  Kf[jp]);
        const float2 Pnjp = cmul(Snjp, Kf[njp]);
        float2 Gj, Gnj, Gjp, Gnjp;
        repack(Pj,  Pnj,  W16,  Gj,  Gnj);
        repack(Pjp, Pnjp, W16p, Gjp, Gnjp);
        // inverse radix-2 fold: pair (P1,P1+1) holds freqs (j, j+4096); (P2,P2+1): (4096-j, 8192-j)
        b[a1i] = padd(Gj,  Gnjp);
        b[b1i] = psub(Gj,  Gnjp);
        b[a2i] = padd(Gjp, Gnj);
        b[b2i] = psub(Gjp, Gnj);
    }
    __syncthreads();

    // inverse: in-place DIT, spans 2/16/128, last span-1024 stage fused with epilogue
    stage_ip<1, 1>(b, tw, tid);
    stage_ip<1, 4>(b, tw, tid);
    stage_ip<1, 7>(b, tw, tid);

    // S1^-1 (span 1024) + epilogue: need only outputs m=0..3 (n < 4096)
    {
        float2 w1 = tw[TWP(tid)]; w1.y = -w1.y;
        const float2 w2 = cmul(w1, w1);
        const float2 w3 = cmul(w1, w2);
        const float2 w4 = cmul(w2, w2);
        const float2 w5 = cmul(w2, w3);
        const float2 w6 = cmul(w3, w3);
        const float2 w7 = cmul(w3, w4);
        float2 a[8];
        a[0] = b[PAD(tid)];
        a[1] = cmul(w1, b[PAD(tid + 1*1024)]);
        a[2] = cmul(w2, b[PAD(tid + 2*1024)]);
        a[3] = cmul(w3, b[PAD(tid + 3*1024)]);
        a[4] = cmul(w4, b[PAD(tid + 4*1024)]);
        a[5] = cmul(w5, b[PAD(tid + 5*1024)]);
        a[6] = cmul(w6, b[PAD(tid + 6*1024)]);
        a[7] = cmul(w7, b[PAD(tid + 7*1024)]);
        float2 E0,E1,E2,E3, O0,O1,O2,O3;
        dft4p<1>(a[0],a[2],a[4],a[6], E0,E1,E2,E3);
        dft4p<1>(a[1],a[3],a[5],a[7], O0,O1,O2,O3);
        const float c = 0.70710678118654752f;
        const float2 w1O = make_float2(c*(O1.x - O1.y),  c*(O1.x + O1.y));
        const float2 w2O = make_float2(-O2.y, O2.x);
        const float2 w3O = make_float2(-c*(O3.x + O3.y), c*(O3.x - O3.y));
        float2 z0 = padd(E0, O0);
        float2 z1 = padd(E1, w1O);
        float2 z2 = padd(E2, w2O);
        float2 z3 = padd(E3, w3O);
        const float Dd = Dv[d];
        float2* o2 = (float2*)(out + (size_t)row * LSEQ);
        const float2 xv0 = x2[tid];
        const float2 xv1 = x2[tid + 1024];
        const float2 xv2 = x2[tid + 2048];
        const float2 xv3 = x2[tid + 3072];
        o2[tid       ] = make_float2(fmaf(Dd, xv0.x, z0.x), fmaf(Dd, xv0.y, z0.y));
        o2[tid + 1024] = make_float2(fmaf(Dd, xv1.x, z1.x), fmaf(Dd, xv1.y, z1.y));
        o2[tid + 2048] = make_float2(fmaf(Dd, xv2.x, z2.x), fmaf(Dd, xv2.y, z2.y));
        o2[tid + 3072] = make_float2(fmaf(Dd, xv3.x, z3.x), fmaf(Dd, xv3.y, z3.y));
    }
}

// ---------------- launch ----------------
extern "C" void kernel_launch(void* const* d_in, const int* in_sizes, int n_in,
                              void* d_out, int out_size)
{
    const float* x      = (const float*)d_in[0];
    const float* z      = (const float*)d_in[1];
    const float* t      = (const float*)d_in[2];
    const float* freq   = (const float*)d_in[3];
    const float* W1     = (const float*)d_in[4];
    const float* b1     = (const float*)d_in[5];
    const float* W2     = (const float*)d_in[6];
    const float* b2     = (const float*)d_in[7];
    const float* W3     = (const float*)d_in[8];
    const float* b3     = (const float*)d_in[9];
    const float* Wout   = (const float*)d_in[10];
    const float* deltas = (const float*)d_in[11];
    const float* Dv     = (const float*)d_in[12];
    float* out = (float*)d_out;

    cudaFuncSetAttribute(k_kfft, cudaFuncAttributeMaxDynamicSharedMemorySize, SMEM_BYTES);
    cudaFuncSetAttribute(k_conv, cudaFuncAttributeMaxDynamicSharedMemorySize, SMEM_BYTES);

    k_mlp <<<LSEQ / 4, 256>>>(z, freq, W1, b1, W2, b2, W3, b3);
    k_wout<<<LSEQ / 16, 256>>>(Wout, t, deltas);
    k_kfft<<<DM, TFFT, SMEM_BYTES>>>();
    k_conv<<<BATCH * DM, TFFT, SMEM_BYTES>>>(x, Dv, out);
}

// round 10
// speedup vs baseline: 2.2289x; 1.0052x over previous
#include <cuda_runtime.h>
#include <cuda_fp16.h>
#include <math.h>
#include <stdint.h>

#define NFFT 8192
#define LSEQ 8192
#define DM   768
#define BATCH 4
#define TFFT 1024
// In-place buffer pad: breaks stride-1024/128/16 conflicts; all FFT data stages conflict-free.
#define PAD(a) ((a) + ((a) >> 4) + ((a) >> 9))
#define BUFSZ 8720   // PAD(8191)=8717
// Twiddle table pad: makes strided tw reads (idx = 8t, 64t) conflict-free.
#define TWP(j) ((j) + ((j) >> 3) + ((j) >> 6))
#define TWSZ  1170   // TWP(1024)=1168
#define SMEM_BYTES ((BUFSZ + TWSZ) * (int)sizeof(float2))  // 79120

// ---------------- scratch (device globals; no runtime allocation) ----------------
__device__ __align__(16) float   g_h3[LSEQ * 64];
__device__ __align__(16) float   g_k [DM * LSEQ];
__device__ __align__(16) __half2 g_Kf[DM * 8200];   // half-spectra 0..8192 (fp16), stride 8200

// ---------------- packed f32x2 helpers ----------------
__device__ __forceinline__ float2 padd(float2 a, float2 b) {
    float2 r;
    asm("{\n\t.reg .b64 pa, pb, pc;\n\t"
        "mov.b64 pa, {%2, %3};\n\tmov.b64 pb, {%4, %5};\n\t"
        "add.rn.f32x2 pc, pa, pb;\n\tmov.b64 {%0, %1}, pc;\n\t}"
        : "=f"(r.x), "=f"(r.y) : "f"(a.x), "f"(a.y), "f"(b.x), "f"(b.y));
    return r;
}
__device__ __forceinline__ float2 psub(float2 a, float2 b) {
    float2 r;
    asm("{\n\t.reg .b64 pa, pb, pc;\n\t"
        "mov.b64 pa, {%2, %3};\n\tmov.b64 pb, {%4, %5};\n\t"
        "sub.rn.f32x2 pc, pa, pb;\n\tmov.b64 {%0, %1}, pc;\n\t}"
        : "=f"(r.x), "=f"(r.y) : "f"(a.x), "f"(a.y), "f"(b.x), "f"(b.y));
    return r;
}

__device__ __forceinline__ float2 cmul(float2 a, float2 b) {
    return make_float2(a.x*b.x - a.y*b.y, a.x*b.y + a.y*b.x);
}
// complex square: (x+iy)^2 = ((x+y)(x-y), 2xy) — 3 instrs vs 4
__device__ __forceinline__ float2 csqr(float2 a) {
    return make_float2((a.x + a.y) * (a.x - a.y), 2.0f * a.x * a.y);
}

__device__ __forceinline__ float2 h2f(__half2 h) {
    const float2 f = __half22float2(h);
    return make_float2(f.x, f.y);
}

// DFT4 (packed): w = -i (fwd) / +i (inv)
template<int INV>
__device__ __forceinline__ void dft4p(float2 b0, float2 b1, float2 b2, float2 b3,
                                      float2& c0, float2& c1, float2& c2, float2& c3)
{
    const float2 apc = padd(b0, b2), amc = psub(b0, b2);
    const float2 bpd = padd(b1, b3), bmd = psub(b1, b3);
    c0 = padd(apc, bpd);
    c2 = psub(apc, bpd);
    const float2 ib = make_float2(-bmd.y, bmd.x);
    if (INV) { c1 = padd(amc, ib); c3 = psub(amc, ib); }
    else     { c1 = psub(amc, ib); c3 = padd(amc, ib); }
}

// DFT8 via even/odd split
template<int INV>
__device__ __forceinline__ void dft8(const float2 a[8], float2 Y[8])
{
    float2 E0,E1,E2,E3, O0,O1,O2,O3;
    dft4p<INV>(a[0],a[2],a[4],a[6], E0,E1,E2,E3);
    dft4p<INV>(a[1],a[3],a[5],a[7], O0,O1,O2,O3);
    const float c = 0.70710678118654752f;
    float2 w1O, w2O, w3O;
    if (INV) {
        w1O = make_float2(c*(O1.x - O1.y),  c*(O1.x + O1.y));
        w2O = make_float2(-O2.y, O2.x);
        w3O = make_float2(-c*(O3.x + O3.y), c*(O3.x - O3.y));
    } else {
        w1O = make_float2(c*(O1.x + O1.y),  c*(O1.y - O1.x));
        w2O = make_float2(O2.y, -O2.x);
        w3O = make_float2(c*(O3.y - O3.x), -c*(O3.x + O3.y));
    }
    Y[0]=padd(E0,O0);  Y[4]=psub(E0,O0);
    Y[1]=padd(E1,w1O); Y[5]=psub(E1,w1O);
    Y[2]=padd(E2,w2O); Y[6]=psub(E2,w2O);
    Y[3]=padd(E3,w3O); Y[7]=psub(E3,w3O);
}

// In-place DIF/DIT radix-8 stage. LSS = log2(span).
template<int INV, int LSS>
__device__ __forceinline__ void stage_ip(float2* b, const float2* __restrict__ tw, const int tid)
{
    const int S = 1 << LSS;
    int i, e0;
    if (LSS == 1) {
        i  = tid >> 9;                 // 0..1
        const int grp = tid & 511;
        e0 = (grp << 4) + i;
    } else {
        i  = tid & (S - 1);
        e0 = ((tid >> LSS) << (LSS + 3)) + i;
    }
    float2 w1 = tw[TWP(i << (10 - LSS))];
    if (INV) w1.y = -w1.y;
    const float2 w2 = csqr(w1);
    const float2 w3 = cmul(w1, w2);
    const float2 w4 = csqr(w2);
    const float2 w5 = cmul(w2, w3);
    const float2 w6 = csqr(w3);
    const float2 w7 = cmul(w3, w4);
    float2 a[8];
    #pragma unroll
    for (int m = 0; m < 8; m++) a[m] = b[PAD(e0 + m * S)];
    if (INV) {
        a[1]=cmul(w1,a[1]); a[2]=cmul(w2,a[2]); a[3]=cmul(w3,a[3]);
        a[4]=cmul(w4,a[4]); a[5]=cmul(w5,a[5]); a[6]=cmul(w6,a[6]); a[7]=cmul(w7,a[7]);
    }
    float2 Y[8];
    dft8<INV>(a, Y);
    if (!INV) {
        Y[1]=cmul(w1,Y[1]); Y[2]=cmul(w2,Y[2]); Y[3]=cmul(w3,Y[3]);
        Y[4]=cmul(w4,Y[4]); Y[5]=cmul(w5,Y[5]); Y[6]=cmul(w6,Y[6]); Y[7]=cmul(w7,Y[7]);
    }
    #pragma unroll
    for (int m = 0; m < 8; m++) b[PAD(e0 + m * S)] = Y[m];
    __syncthreads();
}

// Forward stage 1 (span 1024) fused with gmem load; inputs m=4..7 are zero.
__device__ __forceinline__ void fwd_s1_gmem(const float2* __restrict__ g, float2* b,
                                            const float2* __restrict__ tw, const int tid)
{
    const float2 a0 = g[tid];
    const float2 a1 = g[tid + 1024];
    const float2 a2 = g[tid + 2048];
    const float2 a3 = g[tid + 3072];
    const float2 E0 = padd(a0, a2), E2 = psub(a0, a2);
    const float2 ia2 = make_float2(-a2.y, a2.x);
    const float2 E1 = psub(a0, ia2);
    const float2 E3 = padd(a0, ia2);
    const float2 O0 = padd(a1, a3), O2 = psub(a1, a3);
    const float2 ia3 = make_float2(-a3.y, a3.x);
    const float2 O1 = psub(a1, ia3);
    const float2 O3 = padd(a1, ia3);
    const float c = 0.70710678118654752f;
    const float2 w1O = make_float2(c*(O1.x + O1.y),  c*(O1.y - O1.x));
    const float2 w2O = make_float2(O2.y, -O2.x);
    const float2 w3O = make_float2(c*(O3.y - O3.x), -c*(O3.x + O3.y));
    float2 Y[8];
    Y[0]=padd(E0,O0);  Y[4]=psub(E0,O0);
    Y[1]=padd(E1,w1O); Y[5]=psub(E1,w1O);
    Y[2]=padd(E2,w2O); Y[6]=psub(E2,w2O);
    Y[3]=padd(E3,w3O); Y[7]=psub(E3,w3O);
    const float2 w1 = tw[TWP(tid)];
    const float2 w2 = csqr(w1);
    const float2 w3 = cmul(w1, w2);
    const float2 w4 = csqr(w2);
    const float2 w5 = cmul(w2, w3);
    const float2 w6 = csqr(w3);
    const float2 w7 = cmul(w3, w4);
    b[PAD(tid         )] = Y[0];
    b[PAD(tid + 1*1024)] = cmul(w1, Y[1]);
    b[PAD(tid + 2*1024)] = cmul(w2, Y[2]);
    b[PAD(tid + 3*1024)] = cmul(w3, Y[3]);
    b[PAD(tid + 4*1024)] = cmul(w4, Y[4]);
    b[PAD(tid + 5*1024)] = cmul(w5, Y[5]);
    b[PAD(tid + 6*1024)] = cmul(w6, Y[6]);
    b[PAD(tid + 7*1024)] = cmul(w7, Y[7]);
    __syncthreads();
}

__device__ __forceinline__ void build_twiddles(float2* tw, int tid)
{
    for (int j = tid; j < 1025; j += TFFT) {
        float s, c;
        sincosf(-6.283185307179586f * (float)j * (1.0f / 8192.0f), &s, &c);
        tw[TWP(j)] = make_float2(c, s);
    }
    __syncthreads();
}

// rfft unpack: S[j] = E + T, S[N-j] = conj(E - T); W16 = e^{-i pi j/N}
__device__ __forceinline__ void rfft_pair(float2 Cj, float2 Cn, float2 W16,
                                          float2& Sj, float2& Snj)
{
    const float2 E = make_float2(0.5f*(Cj.x + Cn.x), 0.5f*(Cj.y - Cn.y));
    const float2 O = make_float2(0.5f*(Cj.y + Cn.y), -0.5f*(Cj.x - Cn.x));
    const float2 T = cmul(W16, O);
    Sj  = padd(E, T);
    const float2 emt = psub(E, T);
    Snj = make_float2(emt.x, -emt.y);
}

// repack: G[j], G[nj] from Pj = S[j]*K[j], Pn = S[nj]*K[nj]
__device__ __forceinline__ void repack(float2 Pj, float2 Pn, float2 W16,
                                       float2& Gj, float2& Gn)
{
    {
        const float2 U  = make_float2(Pj.x + Pn.x, Pj.y - Pn.y);
        const float2 Wd = make_float2(Pj.x - Pn.x, Pj.y + Pn.y);
        const float2 V  = make_float2(W16.x, -W16.y);
        const float2 VW = cmul(V, Wd);
        Gj = make_float2(U.x - VW.y, U.y + VW.x);
    }
    {
        const float2 U  = make_float2(Pn.x + Pj.x, Pn.y - Pj.y);
        const float2 Wd = make_float2(Pn.x - Pj.x, Pn.y + Pj.y);
        const float2 V  = make_float2(-W16.x, -W16.y);
        const float2 VW = cmul(V, Wd);
        Gn = make_float2(U.x - VW.y, U.y + VW.x);
    }
}

// digit-scrambled position of frequency j (<4096): pair (p, p+1) holds (j, j+4096)
__device__ __forceinline__ int pmap(int j) {
    return ((j & 7) << 10) + (((j >> 3) & 7) << 7) + (((j >> 6) & 7) << 4) + (((j >> 9) & 7) << 1);
}

// e^{-i pi/8192}
#define W0X 0.99999992646571789f
#define W0Y (-3.8349518757139556e-4f)

// ---------------- kernel A1: MLP layers 1-3 ----------------
__global__ void k_mlp(const float* __restrict__ z, const float* __restrict__ freq,
                      const float* __restrict__ W1, const float* __restrict__ b1,
                      const float* __restrict__ W2, const float* __restrict__ b2,
                      const float* __restrict__ W3, const float* __restrict__ b3)
{
    __shared__ float zs [4][33];
    __shared__ float hs [4][64];
    __shared__ float hs2[4][64];
    const int f = threadIdx.x & 63;
    const int g = threadIdx.x >> 6;
    const int l = blockIdx.x * 4 + g;

    if (f < 33) zs[g][f] = z[l * 33 + f];
    __syncthreads();

    const float fr = freq[f];
    float acc = b1[f];
    #pragma unroll
    for (int e = 0; e < 33; e++) acc = fmaf(zs[g][e], W1[e * 64 + f], acc);
    hs[g][f] = sinf(fr * acc);
    __syncthreads();

    acc = b2[f];
    #pragma unroll
    for (int e = 0; e < 64; e++) acc = fmaf(hs[g][e], W2[e * 64 + f], acc);
    hs2[g][f] = sinf(fr * acc);
    __syncthreads();

    acc = b3[f];
    #pragma unroll
    for (int e = 0; e < 64; e++) acc = fmaf(hs2[g][e], W3[e * 64 + f], acc);
    g_h3[l * 64 + f] = sinf(fr * acc);
}

// ---------------- kernel A2: k = (h3 @ Wout) * window, transposed to d-major ----
__global__ void k_wout(const float* __restrict__ Wout, const float* __restrict__ t,
                       const float* __restrict__ deltas)
{
    __shared__ float h3s[16 * 64];
    __shared__ float ts[16];
    const int tid = threadIdx.x;
    const int l0 = blockIdx.x * 16;

    for (int i = tid; i < 1024; i += 256) h3s[i] = g_h3[l0 * 64 + i];
    if (tid < 16) ts[tid] = t[l0 + tid];
    __syncthreads();

    float acc[3][16];
    #pragma unroll
    for (int j = 0; j < 3; j++)
        #pragma unroll
        for (int l = 0; l < 16; l++) acc[j][l] = 0.0f;

    #pragma unroll 4
    for (int f = 0; f < 64; f++) {
        const float w0 = Wout[f * 768 + tid];
        const float w1 = Wout[f * 768 + tid + 256];
        const float w2 = Wout[f * 768 + tid + 512];
        #pragma unroll
        for (int l = 0; l < 16; l++) {
            const float h = h3s[l * 64 + f];
            acc[0][l] = fmaf(h, w0, acc[0][l]);
            acc[1][l] = fmaf(h, w1, acc[1][l]);
            acc[2][l] = fmaf(h, w2, acc[2][l]);
        }
    }

    #pragma unroll
    for (int j = 0; j < 3; j++) {
        const int d = tid + j * 256;
        const float ad = fabsf(deltas[d]);
        float v[16];
        #pragma unroll
        for (int l = 0; l < 16; l++)
            v[l] = acc[j][l] * (expf(-ts[l] * ad) + 0.05f);
        float4* dst = (float4*)(g_k + (size_t)d * LSEQ + l0);
        dst[0] = make_float4(v[0],  v[1],  v[2],  v[3]);
        dst[1] = make_float4(v[4],  v[5],  v[6],  v[7]);
        dst[2] = make_float4(v[8],  v[9],  v[10], v[11]);
        dst[3] = make_float4(v[12], v[13], v[14], v[15]);
    }
}

// ---------------- kernel B: Kf[d][j] = rfft(k_d, 16384)[j] / 16384 (fp16 store) ------
__global__ void __launch_bounds__(TFFT, 2) k_kfft()
{
    extern __shared__ float2 smem[];
    float2* b  = smem;
    float2* tw = smem + BUFSZ;
    const int tid = threadIdx.x;
    const int d = blockIdx.x;

    build_twiddles(tw, tid);
    const float2* kr = (const float2*)(g_k + (size_t)d * LSEQ);

    fwd_s1_gmem(kr, b, tw, tid);
    stage_ip<0, 7>(b, tw, tid);
    stage_ip<0, 4>(b, tw, tid);
    stage_ip<0, 1>(b, tw, tid);
    // scrambled radix-8 partials in b; final radix-2 fused into the unpack below

    __half2* Kf = g_Kf + (size_t)d * 8200;
    const float sc = 1.0f / 16384.0f;

    if (tid == 0) {
        const float2 u = b[PAD(0)], v = b[PAD(1)];
        const float2 C0 = padd(u, v);
        const float2 Cm = psub(u, v);          // C[4096]
        Kf[0]    = __floats2half2_rn((C0.x + C0.y) * sc, 0.f);
        Kf[8192] = __floats2half2_rn((C0.x - C0.y) * sc, 0.f);
        Kf[4096] = __floats2half2_rn(Cm.x * sc, -Cm.y * sc);
    }
    #pragma unroll
    for (int it = 0; it < 2; it++) {
        const int j  = tid + 1 + it * 1024;     // 1..2048
        const int jp = 4096 - j;
        const int nj = 8192 - j;
        const int njp = 4096 + j;
        const int P1 = pmap(j);
        const int P2 = pmap(jp);
        const float2 u1 = b[PAD(P1)], v1 = b[PAD(P1 + 1)];
        const float2 u2 = b[PAD(P2)], v2 = b[PAD(P2 + 1)];
        const float2 Cj   = padd(u1, v1);
        const float2 Cnjp = psub(u1, v1);
        const float2 Cjp  = padd(u2, v2);
        const float2 Cnj  = psub(u2, v2);
        float2 W16 = tw[TWP(j >> 1)];
        if (j & 1) W16 = cmul(W16, make_float2(W0X, W0Y));
        const float2 W16p = make_float2(-W16.y, -W16.x);   // W16(4096-j)
        float2 Sj, Snj, Sjp, Snjp;
        rfft_pair(Cj,  Cnj,  W16,  Sj,  Snj);
        rfft_pair(Cjp, Cnjp, W16p, Sjp, Snjp);
        Kf[j]   = __floats2half2_rn(Sj.x * sc,   Sj.y * sc);
        Kf[nj]  = __floats2half2_rn(Snj.x * sc,  Snj.y * sc);
        Kf[jp]  = __floats2half2_rn(Sjp.x * sc,  Sjp.y * sc);
        Kf[njp] = __floats2half2_rn(Snjp.x * sc, Snjp.y * sc);
    }
}

// ---------------- kernel C: per-row fused rFFT -> multiply -> irFFT -> +D*x --------
__global__ void __launch_bounds__(TFFT, 2) k_conv(const float* __restrict__ x,
                                                  const float* __restrict__ Dv,
                                                  float* __restrict__ out)
{
    extern __shared__ float2 smem[];
    float2* b  = smem;
    float2* tw = smem + BUFSZ;
    const int tid = threadIdx.x;
    const int row = blockIdx.x;
    const int d = row % DM;

    build_twiddles(tw, tid);
    const float2* x2 = (const float2*)(x + (size_t)row * LSEQ);

    // forward: in-place DIF, spans 1024/128/16/2 (final radix-2 fused below)
    fwd_s1_gmem(x2, b, tw, tid);
    stage_ip<0, 7>(b, tw, tid);
    stage_ip<0, 4>(b, tw, tid);
    stage_ip<0, 1>(b, tw, tid);

    // spectral (in-place): fold fwd radix-2, unpack, *Kf, repack, fold inv radix-2
    const __half2* __restrict__ Kf = g_Kf + (size_t)d * 8200;

    if (tid == 0) {
        const float2 u = b[PAD(0)], v = b[PAD(1)];
        const float2 C0 = padd(u, v);
        const float2 Cm = psub(u, v);                       // C[4096]
        const float S0 = C0.x + C0.y;
        const float SN = C0.x - C0.y;
        const float2 K0 = h2f(Kf[0]);
        const float2 KN = h2f(Kf[8192]);
        const float2 P0 = make_float2(S0 * K0.x, S0 * K0.y);
        const float2 PN = make_float2(SN * KN.x, SN * KN.y);
        const float2 U = padd(P0, PN);
        const float2 W = psub(P0, PN);
        const float2 G0 = make_float2(U.x - W.y, U.y + W.x);
        const float2 Sm = make_float2(Cm.x, -Cm.y);
        const float2 Pm = cmul(Sm, h2f(Kf[4096]));
        const float2 G4096 = make_float2(2.0f * Pm.x, -2.0f * Pm.y);
        b[PAD(0)] = padd(G0, G4096);
        b[PAD(1)] = psub(G0, G4096);
    }
    #pragma unroll
    for (int it = 0; it < 2; it++) {
        const int j  = tid + 1 + it * 1024;     // 1..2048 (j=2048 self-paired, idempotent)
        const int jp = 4096 - j;
        const int nj = 8192 - j;
        const int njp = 4096 + j;
        const int P1 = pmap(j);
        const int P2 = pmap(jp);
        const int a1i = PAD(P1), b1i = PAD(P1 + 1);
        const int a2i = PAD(P2), b2i = PAD(P2 + 1);
        const float2 u1 = b[a1i], v1 = b[b1i];
        const float2 u2 = b[a2i], v2 = b[b2i];
        const float2 Cj   = padd(u1, v1);   // C[j]
        const float2 Cnjp = psub(u1, v1);   // C[j+4096]
        const float2 Cjp  = padd(u2, v2);   // C[4096-j]
        const float2 Cnj  = psub(u2, v2);   // C[8192-j]
        float2 W16 = tw[TWP(j >> 1)];
        if (j & 1) W16 = cmul(W16, make_float2(W0X, W0Y));
        const float2 W16p = make_float2(-W16.y, -W16.x);
        float2 Sj, Snj, Sjp, Snjp;
        rfft_pair(Cj,  Cnj,  W16,  Sj,  Snj);
        rfft_pair(Cjp, Cnjp, W16p, Sjp, Snjp);
        const float2 Pj   = cmul(Sj,   h2f(Kf[j]));
        const float2 Pnj  = cmul(Snj,  h2f(Kf[nj]));
        const float2 Pjp  = cmul(Sjp,  h2f(Kf[jp]));
        const float2 Pnjp = cmul(Snjp, h2f(Kf[njp]));
        float2 Gj, Gnj, Gjp, Gnjp;
        repack(Pj,  Pnj,  W16,  Gj,  Gnj);
        repack(Pjp, Pnjp, W16p, Gjp, Gnjp);
        // inverse radix-2 fold: pair (P1,P1+1) holds freqs (j, j+4096); (P2,P2+1): (4096-j, 8192-j)
        b[a1i] = padd(Gj,  Gnjp);
        b[b1i] = psub(Gj,  Gnjp);
        b[a2i] = padd(Gjp, Gnj);
        b[b2i] = psub(Gjp, Gnj);
    }
    __syncthreads();

    // inverse: in-place DIT, spans 2/16/128, last span-1024 stage fused with epilogue
    stage_ip<1, 1>(b, tw, tid);
    stage_ip<1, 4>(b, tw, tid);
    stage_ip<1, 7>(b, tw, tid);

    // S1^-1 (span 1024) + epilogue: need only outputs m=0..3 (n < 4096)
    {
        float2 w1 = tw[TWP(tid)]; w1.y = -w1.y;
        const float2 w2 = csqr(w1);
        const float2 w3 = cmul(w1, w2);
        const float2 w4 = csqr(w2);
        const float2 w5 = cmul(w2, w3);
        const float2 w6 = csqr(w3);
        const float2 w7 = cmul(w3, w4);
        float2 a[8];
        a[0] = b[PAD(tid)];
        a[1] = cmul(w1, b[PAD(tid + 1*1024)]);
        a[2] = cmul(w2, b[PAD(tid + 2*1024)]);
        a[3] = cmul(w3, b[PAD(tid + 3*1024)]);
        a[4] = cmul(w4, b[PAD(tid + 4*1024)]);
        a[5] = cmul(w5, b[PAD(tid + 5*1024)]);
        a[6] = cmul(w6, b[PAD(tid + 6*1024)]);
        a[7] = cmul(w7, b[PAD(tid + 7*1024)]);
        float2 E0,E1,E2,E3, O0,O1,O2,O3;
        dft4p<1>(a[0],a[2],a[4],a[6], E0,E1,E2,E3);
        dft4p<1>(a[1],a[3],a[5],a[7], O0,O1,O2,O3);
        const float c = 0.70710678118654752f;
        const float2 w1O = make_float2(c*(O1.x - O1.y),  c*(O1.x + O1.y));
        const float2 w2O = make_float2(-O2.y, O2.x);
        const float2 w3O = make_float2(-c*(O3.x + O3.y), c*(O3.x - O3.y));
        float2 z0 = padd(E0, O0);
        float2 z1 = padd(E1, w1O);
        float2 z2 = padd(E2, w2O);
        float2 z3 = padd(E3, w3O);
        const float Dd = Dv[d];
        float2* o2 = (float2*)(out + (size_t)row * LSEQ);
        const float2 xv0 = x2[tid];
        const float2 xv1 = x2[tid + 1024];
        const float2 xv2 = x2[tid + 2048];
        const float2 xv3 = x2[tid + 3072];
        o2[tid       ] = make_float2(fmaf(Dd, xv0.x, z0.x), fmaf(Dd, xv0.y, z0.y));
        o2[tid + 1024] = make_float2(fmaf(Dd, xv1.x, z1.x), fmaf(Dd, xv1.y, z1.y));
        o2[tid + 2048] = make_float2(fmaf(Dd, xv2.x, z2.x), fmaf(Dd, xv2.y, z2.y));
        o2[tid + 3072] = make_float2(fmaf(Dd, xv3.x, z3.x), fmaf(Dd, xv3.y, z3.y));
    }
}

// ---------------- launch ----------------
extern "C" void kernel_launch(void* const* d_in, const int* in_sizes, int n_in,
                              void* d_out, int out_size)
{
    const float* x      = (const float*)d_in[0];
    const float* z      = (const float*)d_in[1];
    const float* t      = (const float*)d_in[2];
    const float* freq   = (const float*)d_in[3];
    const float* W1     = (const float*)d_in[4];
    const float* b1     = (const float*)d_in[5];
    const float* W2     = (const float*)d_in[6];
    const float* b2     = (const float*)d_in[7];
    const float* W3     = (const float*)d_in[8];
    const float* b3     = (const float*)d_in[9];
    const float* Wout   = (const float*)d_in[10];
    const float* deltas = (const float*)d_in[11];
    const float* Dv     = (const float*)d_in[12];
    float* out = (float*)d_out;

    cudaFuncSetAttribute(k_kfft, cudaFuncAttributeMaxDynamicSharedMemorySize, SMEM_BYTES);
    cudaFuncSetAttribute(k_conv, cudaFuncAttributeMaxDynamicSharedMemorySize, SMEM_BYTES);

    k_mlp <<<LSEQ / 4, 256>>>(z, freq, W1, b1, W2, b2, W3, b3);
    k_wout<<<LSEQ / 16, 256>>>(Wout, t, deltas);
    k_kfft<<<DM, TFFT, SMEM_BYTES>>>();
    k_conv<<<BATCH * DM, TFFT, SMEM_BYTES>>>(x, Dv, out);
}